// round 5
// baseline (speedup 1.0000x reference)
#include <cuda_runtime.h>
#include <math.h>

#define B_ 8
#define C_ 64
#define L_ 2048
#define CS_ 256
#define HD_ 64
#define NN_ (B_*CS_*L_)      // 4194304
#define NC_ (B_*C_*L_)       // 1048576
#define NEVAL_ 25

// ---------------- scratch (device globals; no runtime allocation) ----------------
__device__ float g_stacked[NN_];
__device__ float g_y[NN_];
__device__ float g_s[6][NN_];
__device__ float g_apA[NC_];
__device__ float g_apB[NC_];
__device__ float g_amax[B_*C_];
__device__ float g_filt[16];
__device__ float g_gb[NEVAL_*128];
__device__ double g_part[B_*64];

typedef unsigned long long ull;

__device__ __forceinline__ float gelu_f(float x){
    return 0.5f * x * (1.0f + erff(x * 0.70710678118654752440f));
}
__device__ __forceinline__ ull bcast2(float x){
    ull r; asm("mov.b64 %0, {%1, %1};" : "=l"(r) : "f"(x)); return r;
}
__device__ __forceinline__ ull pk2(float a, float b){
    ull r; asm("mov.b64 %0, {%1, %2};" : "=l"(r) : "f"(a), "f"(b)); return r;
}
__device__ __forceinline__ void fma2(ull &d, ull a, ull b){
    asm("fma.rn.f32x2 %0, %1, %2, %0;" : "+l"(d) : "l"(a), "l"(b));
}
__device__ __forceinline__ float2 unpk(ull v){
    float lo, hi; asm("mov.b64 {%0, %1}, %2;" : "=f"(lo), "=f"(hi) : "l"(v));
    return make_float2(lo, hi);
}

// ---------------- wavelet part ----------------
__global__ void kcopyx(const float* __restrict__ x, float* __restrict__ stacked){
    int i = blockIdx.x*256 + threadIdx.x;
    int l = i & (L_-1); int bc = i >> 11; int c = bc & 63; int b = bc >> 6;
    stacked[(((b*CS_) + c) << 11) + l] = x[i];
}

__global__ void kmax(const float* __restrict__ src, float* __restrict__ amax){
    int row = blockIdx.x;
    const float* p = src + (size_t)row * L_;
    float m = -3.4e38f;
    for (int i = threadIdx.x; i < L_; i += 256) m = fmaxf(m, p[i]);
    __shared__ float sm[256];
    sm[threadIdx.x] = m; __syncthreads();
    for (int s = 128; s > 0; s >>= 1){
        if (threadIdx.x < s) sm[threadIdx.x] = fmaxf(sm[threadIdx.x], sm[threadIdx.x+s]);
        __syncthreads();
    }
    if (threadIdx.x == 0) amax[row] = sm[0];
}

__global__ void kdywan(const float* __restrict__ amax,
                       const float* __restrict__ sw1, const float* __restrict__ sb1,
                       const float* __restrict__ sw2, const float* __restrict__ sb2,
                       const float* __restrict__ sw3, const float* __restrict__ sb3,
                       float* __restrict__ filt){
    __shared__ float feat[8*32], g2[8*32], raw[8*16], nrm[16];
    int t = threadIdx.x;
    { int b = t >> 5, h = t & 31;
      float s = sb1[h];
      const float* am = amax + b*64; const float* w = sw1 + h*64;
      #pragma unroll 8
      for (int c = 0; c < 64; c++) s += am[c]*w[c];
      feat[t] = gelu_f(s); }
    __syncthreads();
    { int b = t >> 5, h = t & 31;
      float s = sb2[h];
      #pragma unroll 8
      for (int k = 0; k < 32; k++) s += feat[b*32+k]*sw2[h*32+k];
      g2[t] = gelu_f(s); }
    __syncthreads();
    if (t < 128){ int b = t >> 4, j = t & 15;
      float s = sb3[j];
      #pragma unroll 8
      for (int k = 0; k < 32; k++) s += g2[b*32+k]*sw3[j*32+k];
      raw[t] = s; }
    __syncthreads();
    if (t < 16){ int b = t >> 1, hh = t & 1;
      float s = 0.f;
      for (int j = 0; j < 8; j++){ float v = raw[b*16 + hh*8 + j]; s += v*v; }
      nrm[t] = sqrtf(s); }
    __syncthreads();
    if (t < 16){ int hh = t >> 3, j = t & 7;
      float s = 0.f;
      for (int b = 0; b < 8; b++) s += raw[b*16 + hh*8 + j] / nrm[b*2 + hh];
      filt[hh*8 + j] = s * 0.125f; }
}

__global__ void kwav(const float* __restrict__ src, const float* __restrict__ filt,
                     float* __restrict__ apOut, float* __restrict__ stacked, int chOff){
    int i = blockIdx.x*256 + threadIdx.x;
    int l = i & (L_-1); int bc = i >> 11; int c = bc & 63; int b = bc >> 6;
    const float* row = src + (size_t)bc * L_;
    float alo = 0.f, ahi = 0.f;
    #pragma unroll
    for (int k = 0; k < 8; k++){
        int o = l + k - 3;
        if (o < 0) o = -o;
        if (o >= L_) o = 2*L_ - 2 - o;
        float v = row[o];
        alo += v * filt[k];
        ahi += v * filt[8 + k];
    }
    apOut[i] = alo;
    stacked[(((size_t)b*CS_ + chOff + c) << 11) + l] = ahi;
}

// ---------------- time MLP: gamma/beta for all 25 evals ----------------
__global__ void kgb(const float* __restrict__ tw1, const float* __restrict__ tb1,
                    const float* __restrict__ tw2, const float* __restrict__ tb2,
                    const float* __restrict__ cw,  const float* __restrict__ cb,
                    float* __restrict__ gb){
    int e = blockIdx.x;
    const double hs = 0.25;
    double td;
    if (e == 24) td = 1.0;
    else {
        int i = e / 6, s = e % 6;
        double off;
        switch (s){
            case 0: off = 0.0; break;
            case 1: off = hs/5.0; break;
            case 2: off = 3.0*hs/10.0; break;
            case 3: off = 4.0*hs/5.0; break;
            case 4: off = 8.0*hs/9.0; break;
            default: off = hs; break;
        }
        td = (double)i*hs + off;
    }
    float t = (float)td;
    __shared__ float te1[16], te2[16];
    int tid = threadIdx.x;
    if (tid < 16) te1[tid] = gelu_f(t * tw1[tid] + tb1[tid]);
    __syncthreads();
    if (tid < 16){
        float s = tb2[tid];
        #pragma unroll
        for (int k = 0; k < 16; k++) s += te1[k]*tw2[tid*16+k];
        te2[tid] = s;
    }
    __syncthreads();
    float s = cb[tid];
    #pragma unroll
    for (int k = 0; k < 16; k++) s += te2[k]*cw[tid*16+k];
    gb[e*128 + tid] = s;
}

// ---------------- fused ode_f: conv1(FiLM,GELU) -> conv2(GELU) -> conv3 ----------------
// block: 288 threads = 16 ct x 18 lt; out l-tile = 64; grid (32, 8)
// smem: xs[32][76] | h1s[64][76] | h2s[64][76] | ws[64][3][64]
#define XS_STR 76
#define SM_XS   0
#define SM_H1   (32*76)
#define SM_H2   (SM_H1 + 64*76)
#define SM_WS   (SM_H2 + 64*76)
#define SM_TOT  ((SM_WS + 64*192) * 4)   // bytes = 97792

// accumulate 4co x 4l conv window over nci input channels from smem
template<int NCI>
__device__ __forceinline__ void accum_tile(const float* __restrict__ xsm,
                                           const float* __restrict__ wsm,
                                           int co0, int l0, ull acc[2][4]){
    #pragma unroll 4
    for (int ci = 0; ci < NCI; ci++){
        const float* xr = xsm + ci*XS_STR + l0;
        float4 xa = *(const float4*)xr;
        float2 xb = *(const float2*)(xr + 4);
        ull xq[6];
        xq[0]=bcast2(xa.x); xq[1]=bcast2(xa.y); xq[2]=bcast2(xa.z);
        xq[3]=bcast2(xa.w); xq[4]=bcast2(xb.x); xq[5]=bcast2(xb.y);
        const float* wr = wsm + ci*192 + co0;
        #pragma unroll
        for (int k = 0; k < 3; k++){
            float4 wv = *(const float4*)(wr + k*64);
            ull wp0 = pk2(wv.x, wv.y), wp1 = pk2(wv.z, wv.w);
            #pragma unroll
            for (int l = 0; l < 4; l++){
                fma2(acc[0][l], wp0, xq[l+k]);
                fma2(acc[1][l], wp1, xq[l+k]);
            }
        }
    }
}

__global__ __launch_bounds__(288, 2)
void kfused(const float* __restrict__ y,
            const float* __restrict__ a1, float c1,
            const float* __restrict__ a2, float c2,
            const float* __restrict__ a3, float c3,
            const float* __restrict__ a4, float c4,
            const float* __restrict__ a5, float c5,
            const float* __restrict__ w1, const float* __restrict__ b1v,
            const float* __restrict__ w2, const float* __restrict__ b2v,
            const float* __restrict__ w3, const float* __restrict__ b3v,
            const float* __restrict__ gb,
            float* __restrict__ outp){
    extern __shared__ float sm[];
    float* xs  = sm + SM_XS;
    float* h1s = sm + SM_H1;
    float* h2s = sm + SM_H2;
    float* ws  = sm + SM_WS;

    const int b  = blockIdx.y;
    const int L0 = blockIdx.x * 64;
    const int t  = threadIdx.x;
    const int ct = t & 15;
    const int lt = t >> 4;          // 0..17
    const int co0 = ct * 4;
    const int l0  = lt * 4;

    const size_t inOff = (size_t)b * CS_ * L_;
    const float* yb = y + inOff;
    const float* p1 = a1 ? a1 + inOff : nullptr;
    const float* p2 = a2 ? a2 + inOff : nullptr;
    const float* p3 = a3 ? a3 + inOff : nullptr;
    const float* p4 = a4 ? a4 + inOff : nullptr;
    const float* p5 = a5 ? a5 + inOff : nullptr;

    // -------- stage 1: h1 on slots [0,72) <-> global l = L0-2+i --------
    ull acc[2][4];
    #pragma unroll
    for (int p = 0; p < 2; p++)
        #pragma unroll
        for (int l = 0; l < 4; l++) acc[p][l] = 0ULL;

    for (int c0 = 0; c0 < CS_; c0 += 32){
        __syncthreads();
        // x tile: xs[ci][j], j in [0,76), global l = L0-3+j, zero outside [0,L)
        for (int idx = t; idx < 32*XS_STR; idx += 288){
            int ci = idx / XS_STR, j = idx - ci*XS_STR;
            int gl = L0 - 3 + j;
            float v = 0.f;
            if (j < 70 && gl >= 0 && gl < L_){
                size_t o = (size_t)(c0 + ci) * L_ + gl;
                v = yb[o];
                if (p1) v += c1 * p1[o];
                if (p2) v += c2 * p2[o];
                if (p3) v += c3 * p3[o];
                if (p4) v += c4 * p4[o];
                if (p5) v += c5 * p5[o];
            }
            xs[idx] = v;
        }
        // w1 chunk: ws[ci][k][co]
        for (int idx = t; idx < 32*192; idx += 288){
            int co = idx & 63; int r = idx >> 6;
            int k = r % 3, ci = r / 3;
            ws[ci*192 + k*64 + co] = w1[(size_t)co*(CS_*3) + (c0+ci)*3 + k];
        }
        __syncthreads();
        accum_tile<32>(xs, ws, co0, l0, acc);
    }
    __syncthreads();   // all reads of ws/xs done

    // epilogue 1: bias + FiLM + GELU -> h1s
    // h1 slot i <-> global l = L0-2+i; out-of-range slots MUST be zero
    // (conv2 zero-pads its own input; gelu(FiLM(bias)) of zero x is NOT zero)
    {
        float vals[4][4];
        #pragma unroll
        for (int l = 0; l < 4; l++){
            float2 u0 = unpk(acc[0][l]), u1 = unpk(acc[1][l]);
            vals[0][l]=u0.x; vals[1][l]=u0.y; vals[2][l]=u1.x; vals[3][l]=u1.y;
        }
        #pragma unroll
        for (int c = 0; c < 4; c++){
            int co = co0 + c;
            float bia = b1v[co], ga = gb[co], be = gb[64+co];
            float4 r;
            float* pr = (float*)&r;
            #pragma unroll
            for (int ll = 0; ll < 4; ll++){
                int gl = L0 - 2 + l0 + ll;
                float h = gelu_f((1.f+ga)*(vals[c][ll]+bia)+be);
                pr[ll] = (gl >= 0 && gl < L_) ? h : 0.f;
            }
            *(float4*)&h1s[co*XS_STR + l0] = r;
        }
        // zero pad tail of h1 rows (slots 72..75) once
        if (lt == 17){
            #pragma unroll
            for (int c = 0; c < 4; c++){
                h1s[(co0+c)*XS_STR + 72] = 0.f; h1s[(co0+c)*XS_STR + 73] = 0.f;
                h1s[(co0+c)*XS_STR + 74] = 0.f; h1s[(co0+c)*XS_STR + 75] = 0.f;
            }
        }
    }
    // load w2 (full 64 ci)
    for (int idx = t; idx < 64*192; idx += 288){
        int co = idx & 63; int r = idx >> 6;
        int k = r % 3, ci = r / 3;
        ws[ci*192 + k*64 + co] = w2[(size_t)co*(HD_*3) + ci*3 + k];
    }
    __syncthreads();

    // -------- stage 2: h2 on slots [0,68) <-> global l = L0-1+i --------
    {
        ull acc2[2][4];
        #pragma unroll
        for (int p = 0; p < 2; p++)
            #pragma unroll
            for (int l = 0; l < 4; l++) acc2[p][l] = 0ULL;
        if (lt < 17)
            accum_tile<64>(h1s, ws, co0, l0, acc2);
        __syncthreads();   // stage2 compute done before ws reuse
        if (lt < 17){
            float vals[4][4];
            #pragma unroll
            for (int l = 0; l < 4; l++){
                float2 u0 = unpk(acc2[0][l]), u1 = unpk(acc2[1][l]);
                vals[0][l]=u0.x; vals[1][l]=u0.y; vals[2][l]=u1.x; vals[3][l]=u1.y;
            }
            #pragma unroll
            for (int c = 0; c < 4; c++){
                int co = co0 + c;
                float bia = b2v[co];
                float4 r;
                float* pr = (float*)&r;
                #pragma unroll
                for (int ll = 0; ll < 4; ll++){
                    int gl = L0 - 1 + l0 + ll;   // h2 slot <-> global l
                    float h = gelu_f(vals[c][ll]+bia);
                    pr[ll] = (gl >= 0 && gl < L_) ? h : 0.f;
                }
                *(float4*)&h2s[co*XS_STR + l0] = r;
            }
        }
        if (lt == 17){
            #pragma unroll
            for (int c = 0; c < 4; c++){
                #pragma unroll
                for (int j = 68; j < 76; j++) h2s[(co0+c)*XS_STR + j] = 0.f;
            }
        }
    }
    __syncthreads();

    // -------- stage 3: out on slots [0,64), 4 groups of 64 co --------
    for (int g = 0; g < 4; g++){
        for (int idx = t; idx < 64*192; idx += 288){
            int co = idx & 63; int r = idx >> 6;
            int k = r % 3, ci = r / 3;
            ws[ci*192 + k*64 + co] = w3[(size_t)(g*64+co)*(HD_*3) + ci*3 + k];
        }
        __syncthreads();
        if (lt < 16){
            ull acc3[2][4];
            #pragma unroll
            for (int p = 0; p < 2; p++)
                #pragma unroll
                for (int l = 0; l < 4; l++) acc3[p][l] = 0ULL;
            accum_tile<64>(h2s, ws, co0, l0, acc3);
            float vals[4][4];
            #pragma unroll
            for (int l = 0; l < 4; l++){
                float2 u0 = unpk(acc3[0][l]), u1 = unpk(acc3[1][l]);
                vals[0][l]=u0.x; vals[1][l]=u0.y; vals[2][l]=u1.x; vals[3][l]=u1.y;
            }
            #pragma unroll
            for (int c = 0; c < 4; c++){
                int co = g*64 + co0 + c;
                float bia = b3v[co];
                float4 r = make_float4(vals[c][0]+bia, vals[c][1]+bia,
                                       vals[c][2]+bia, vals[c][3]+bia);
                *(float4*)&outp[((size_t)(b*CS_ + co)) * L_ + L0 + l0] = r;
            }
        }
        __syncthreads();
    }
}

// ---------------- stage combination (final y update), float4 ----------------
__global__ void kcomb(float* __restrict__ dst, const float* __restrict__ y,
                      const float* __restrict__ s1, float c1,
                      const float* __restrict__ s2, float c2,
                      const float* __restrict__ s3, float c3,
                      const float* __restrict__ s4, float c4,
                      const float* __restrict__ s5, float c5){
    int i = blockIdx.x*256 + threadIdx.x;
    float4 v = ((const float4*)y)[i];
    float4 t1 = ((const float4*)s1)[i];
    float4 t2 = ((const float4*)s2)[i];
    float4 t3 = ((const float4*)s3)[i];
    float4 t4 = ((const float4*)s4)[i];
    float4 t5 = ((const float4*)s5)[i];
    v.x += c1*t1.x + c2*t2.x + c3*t3.x + c4*t4.x + c5*t5.x;
    v.y += c1*t1.y + c2*t2.y + c3*t3.y + c4*t4.y + c5*t5.y;
    v.z += c1*t1.z + c2*t2.z + c3*t3.z + c4*t4.z + c5*t5.z;
    v.w += c1*t1.w + c2*t2.w + c3*t3.w + c4*t4.w + c5*t5.w;
    ((float4*)dst)[i] = v;
}

// ---------------- ecloss reduction ----------------
__global__ void kinner(const float* __restrict__ a, const float* __restrict__ d,
                       double* __restrict__ part){
    int bb = blockIdx.x, ch = blockIdx.y;
    size_t base = (size_t)bb*CS_*L_ + (size_t)ch*8192;
    double s = 0.0;
    for (int i = threadIdx.x; i < 8192; i += 256)
        s += (double)a[base+i] * (double)d[base+i];
    __shared__ double sm[256];
    sm[threadIdx.x] = s; __syncthreads();
    for (int st = 128; st > 0; st >>= 1){
        if (threadIdx.x < st) sm[threadIdx.x] += sm[threadIdx.x+st];
        __syncthreads();
    }
    if (threadIdx.x == 0) part[bb*64 + ch] = sm[0];
}

__global__ void kfinal(const double* __restrict__ part, float* __restrict__ out){
    if (threadIdx.x == 0){
        double acc = 0.0;
        for (int b = 0; b < 8; b++){
            double s = 0.0;
            for (int j = 0; j < 64; j++) s += part[b*64+j];
            acc += s*s;
        }
        out[4194304] = (float)(acc / 8.0);
    }
}

// ---------------- output permute ----------------
__global__ void kout(const float* __restrict__ y, float* __restrict__ out){
    int i = blockIdx.x*256 + threadIdx.x;
    int l = i & (L_-1); int bc = i >> 11; int c = bc & 255; int b = bc >> 8;
    int g = c >> 6; int cc = c & 63;
    out[(size_t)g*(B_*C_*L_) + (((size_t)b*C_ + cc) << 11) + l] = y[i];
}

// ---------------- host orchestration ----------------
extern "C" void kernel_launch(void* const* d_in, const int* in_sizes, int n_in,
                              void* d_out, int out_size){
    const float* x   = (const float*)d_in[0];
    const float* sw1 = (const float*)d_in[1];
    const float* sb1 = (const float*)d_in[2];
    const float* sw2 = (const float*)d_in[3];
    const float* sb2 = (const float*)d_in[4];
    const float* sw3 = (const float*)d_in[5];
    const float* sb3 = (const float*)d_in[6];
    const float* tw1 = (const float*)d_in[7];
    const float* tb1 = (const float*)d_in[8];
    const float* tw2 = (const float*)d_in[9];
    const float* tb2 = (const float*)d_in[10];
    const float* cw  = (const float*)d_in[11];
    const float* cb  = (const float*)d_in[12];
    const float* k1  = (const float*)d_in[13];
    const float* kb1 = (const float*)d_in[14];
    const float* k2  = (const float*)d_in[15];
    const float* kb2 = (const float*)d_in[16];
    const float* k3  = (const float*)d_in[17];
    const float* kb3 = (const float*)d_in[18];
    float* out = (float*)d_out;

    float *stacked, *y, *sbase, *apA, *apB, *amax, *filt, *gb;
    double* part;
    cudaGetSymbolAddress((void**)&stacked, g_stacked);
    cudaGetSymbolAddress((void**)&y,       g_y);
    cudaGetSymbolAddress((void**)&sbase,   g_s);
    cudaGetSymbolAddress((void**)&apA,     g_apA);
    cudaGetSymbolAddress((void**)&apB,     g_apB);
    cudaGetSymbolAddress((void**)&amax,    g_amax);
    cudaGetSymbolAddress((void**)&filt,    g_filt);
    cudaGetSymbolAddress((void**)&gb,      g_gb);
    cudaGetSymbolAddress((void**)&part,    g_part);

    cudaFuncSetAttribute(kfused, cudaFuncAttributeMaxDynamicSharedMemorySize, SM_TOT);

    float* S[6];
    for (int k = 0; k < 6; k++) S[k] = sbase + (size_t)k * NN_;

    // ---- wavelet decomposition ----
    kcopyx<<<NC_/256, 256>>>(x, stacked);
    const float* cur = x;
    float* nxt = apA;
    for (int lvl = 0; lvl < 3; lvl++){
        kmax<<<B_*C_, 256>>>(cur, amax);
        kdywan<<<1, 256>>>(amax, sw1, sb1, sw2, sb2, sw3, sb3, filt);
        kwav<<<NC_/256, 256>>>(cur, filt, nxt, stacked, (lvl+1)*64);
        cur = nxt;
        nxt = (nxt == apA) ? apB : apA;
    }
    cudaMemcpyAsync(y, stacked, (size_t)NN_ * sizeof(float), cudaMemcpyDeviceToDevice, 0);

    kgb<<<NEVAL_, 128>>>(tw1, tb1, tw2, tb2, cw, cb, gb);

    const dim3 gF(L_/64, B_), bF(288);

    auto odef = [&](int ev, const float* a1, float c1, const float* a2, float c2,
                    const float* a3, float c3, const float* a4, float c4,
                    const float* a5, float c5, float* sout){
        kfused<<<gF, bF, SM_TOT>>>(y, a1,c1, a2,c2, a3,c3, a4,c4, a5,c5,
                                   k1, kb1, k2, kb2, k3, kb3,
                                   gb + ev*128, sout);
    };

    const double hs = 0.25;
    const float* Z = nullptr;
    for (int st = 0; st < 4; st++){
        int e = st*6;
        odef(e+0, Z,0,Z,0,Z,0,Z,0,Z,0, S[0]);
        odef(e+1, S[0],(float)(hs*1.0/5.0), Z,0,Z,0,Z,0,Z,0, S[1]);
        odef(e+2, S[0],(float)(hs*3.0/40.0), S[1],(float)(hs*9.0/40.0), Z,0,Z,0,Z,0, S[2]);
        odef(e+3, S[0],(float)(hs*44.0/45.0), S[1],(float)(-hs*56.0/15.0),
                  S[2],(float)(hs*32.0/9.0), Z,0,Z,0, S[3]);
        odef(e+4, S[0],(float)(hs*19372.0/6561.0), S[1],(float)(-hs*25360.0/2187.0),
                  S[2],(float)(hs*64448.0/6561.0), S[3],(float)(-hs*212.0/729.0), Z,0, S[4]);
        odef(e+5, S[0],(float)(hs*9017.0/3168.0), S[1],(float)(-hs*355.0/33.0),
                  S[2],(float)(hs*46732.0/5247.0), S[3],(float)(hs*49.0/176.0),
                  S[4],(float)(-hs*5103.0/18656.0), S[5]);
        kcomb<<<NN_/1024,256>>>(y, y, S[0],(float)(hs*35.0/384.0), S[2],(float)(hs*500.0/1113.0),
                          S[3],(float)(hs*125.0/192.0), S[4],(float)(-hs*2187.0/6784.0),
                          S[5],(float)(hs*11.0/84.0));
    }

    // ---- dx = ode_f(1.0, ode_out) ; ecloss ----
    odef(24, Z,0,Z,0,Z,0,Z,0,Z,0, S[0]);
    kinner<<<dim3(B_, 64), 256>>>(stacked, S[0], part);

    // ---- outputs ----
    kout<<<NN_/256, 256>>>(y, out);
    kfinal<<<1, 32>>>(part, out);
}

// round 6
// speedup vs baseline: 1.1314x; 1.1314x over previous
#include <cuda_runtime.h>
#include <math.h>

#define B_ 8
#define C_ 64
#define L_ 2048
#define CS_ 256
#define HD_ 64
#define NN_ (B_*CS_*L_)      // 4194304
#define NC_ (B_*C_*L_)       // 1048576
#define NEVAL_ 25
#define LT_ 56               // l-tile per block
#define NBX_ 37              // 37*56 = 2072 >= 2048

// smem float offsets for kfused
#define XSO 0                // xs: 2 buffers x 32ci x 64 slots = 4096
#define H1O 4096             // h1: 64co x 64 slots
#define H2O 8192             // h2: 64co x 64 slots
#define WSO 12288            // ws: 64ci x 3k x 64co = 12288 (stage1 uses 6144 halves)
#define SM_FLOATS 24576
#define SMB (SM_FLOATS*4)    // 98304 bytes

// ---------------- scratch (device globals; no runtime allocation) ----------------
__device__ float g_stacked[NN_];
__device__ float g_y[NN_];
__device__ float g_s[6][NN_];
__device__ float g_apA[NC_];
__device__ float g_apB[NC_];
__device__ float g_amax[B_*C_];
__device__ float g_gb[NEVAL_*128];
__device__ double g_part[B_*64];

typedef unsigned long long ull;

__device__ __forceinline__ float gelu_f(float x){
    return 0.5f * x * (1.0f + erff(x * 0.70710678118654752440f));
}
__device__ __forceinline__ ull bcast2(float x){
    ull r; asm("mov.b64 %0, {%1, %1};" : "=l"(r) : "f"(x)); return r;
}
__device__ __forceinline__ ull pk2(float a, float b){
    ull r; asm("mov.b64 %0, {%1, %2};" : "=l"(r) : "f"(a), "f"(b)); return r;
}
__device__ __forceinline__ void fma2(ull &d, ull a, ull b){
    asm("fma.rn.f32x2 %0, %1, %2, %0;" : "+l"(d) : "l"(a), "l"(b));
}
__device__ __forceinline__ float2 unpk(ull v){
    float lo, hi; asm("mov.b64 {%0, %1}, %2;" : "=f"(lo), "=f"(hi) : "l"(v));
    return make_float2(lo, hi);
}

// ---------------- prep: row-max of x (blocks 0-511) + time-MLP gamma/beta (blocks 512-536) ----------------
__global__ void kprep(const float* __restrict__ x,
                      const float* __restrict__ tw1, const float* __restrict__ tb1,
                      const float* __restrict__ tw2, const float* __restrict__ tb2,
                      const float* __restrict__ cw,  const float* __restrict__ cb,
                      float* __restrict__ amax, float* __restrict__ gbout){
    if (blockIdx.x < 512){
        int row = blockIdx.x;
        const float* p = x + (size_t)row * L_;
        float m = -3.4e38f;
        for (int i = threadIdx.x; i < L_; i += 256) m = fmaxf(m, p[i]);
        __shared__ float sm[256];
        sm[threadIdx.x] = m; __syncthreads();
        for (int s = 128; s > 0; s >>= 1){
            if (threadIdx.x < s) sm[threadIdx.x] = fmaxf(sm[threadIdx.x], sm[threadIdx.x+s]);
            __syncthreads();
        }
        if (threadIdx.x == 0) amax[row] = sm[0];
    } else {
        int e = blockIdx.x - 512;
        const double hs = 0.25;
        double td;
        if (e == 24) td = 1.0;
        else {
            int i = e / 6, s = e % 6;
            double off;
            switch (s){
                case 0: off = 0.0; break;
                case 1: off = hs/5.0; break;
                case 2: off = 3.0*hs/10.0; break;
                case 3: off = 4.0*hs/5.0; break;
                case 4: off = 8.0*hs/9.0; break;
                default: off = hs; break;
            }
            td = (double)i*hs + off;
        }
        float t = (float)td;
        __shared__ float te1[16], te2[16];
        int tid = threadIdx.x;
        if (tid < 16) te1[tid] = gelu_f(t * tw1[tid] + tb1[tid]);
        __syncthreads();
        if (tid < 16){
            float s = tb2[tid];
            #pragma unroll
            for (int k = 0; k < 16; k++) s += te1[k]*tw2[tid*16+k];
            te2[tid] = s;
        }
        __syncthreads();
        if (tid < 128){
            float s = cb[tid];
            #pragma unroll
            for (int k = 0; k < 16; k++) s += te2[k]*cw[tid*16+k];
            gbout[e*128 + tid] = s;
        }
    }
}

// ---------------- row max for levels 2,3 ----------------
__global__ void kmax(const float* __restrict__ src, float* __restrict__ amax){
    int row = blockIdx.x;
    const float* p = src + (size_t)row * L_;
    float m = -3.4e38f;
    for (int i = threadIdx.x; i < L_; i += 256) m = fmaxf(m, p[i]);
    __shared__ float sm[256];
    sm[threadIdx.x] = m; __syncthreads();
    for (int s = 128; s > 0; s >>= 1){
        if (threadIdx.x < s) sm[threadIdx.x] = fmaxf(sm[threadIdx.x], sm[threadIdx.x+s]);
        __syncthreads();
    }
    if (threadIdx.x == 0) amax[row] = sm[0];
}

// ---------------- fused dywan MLP (per-block redundant) + wavelet conv (+ optional x copy) ----------------
// grid 1024, 256 threads, 4 elements per thread
__global__ void kwavF(const float* __restrict__ src,
                      const float* __restrict__ amax,
                      const float* __restrict__ sw1, const float* __restrict__ sb1,
                      const float* __restrict__ sw2, const float* __restrict__ sb2,
                      const float* __restrict__ sw3, const float* __restrict__ sb3,
                      float* __restrict__ apOut, float* __restrict__ stacked,
                      int chOff, int copyX){
    __shared__ float feat[256], g2s[256], raw[128], nrm[16], filt[16];
    int t = threadIdx.x;
    { int bb = t >> 5, h = t & 31;
      float s = sb1[h];
      const float* am = amax + bb*64; const float* w = sw1 + h*64;
      #pragma unroll 8
      for (int c = 0; c < 64; c++) s += am[c]*w[c];
      feat[t] = gelu_f(s); }
    __syncthreads();
    { int bb = t >> 5, h = t & 31;
      float s = sb2[h];
      #pragma unroll 8
      for (int k = 0; k < 32; k++) s += feat[bb*32+k]*sw2[h*32+k];
      g2s[t] = gelu_f(s); }
    __syncthreads();
    if (t < 128){ int bb = t >> 4, j = t & 15;
      float s = sb3[j];
      #pragma unroll 8
      for (int k = 0; k < 32; k++) s += g2s[bb*32+k]*sw3[j*32+k];
      raw[t] = s; }
    __syncthreads();
    if (t < 16){ int bb = t >> 1, hh = t & 1;
      float s = 0.f;
      for (int j = 0; j < 8; j++){ float v = raw[bb*16 + hh*8 + j]; s += v*v; }
      nrm[t] = sqrtf(s); }
    __syncthreads();
    if (t < 16){ int hh = t >> 3, j = t & 7;
      float s = 0.f;
      for (int bb = 0; bb < 8; bb++) s += raw[bb*16 + hh*8 + j] / nrm[bb*2 + hh];
      filt[hh*8 + j] = s * 0.125f; }
    __syncthreads();

    #pragma unroll 1
    for (int r = 0; r < 4; r++){
        int i = (blockIdx.x << 10) + (r << 8) + t;
        int l = i & (L_-1); int bc = i >> 11; int c = bc & 63; int bb = bc >> 6;
        const float* row = src + (size_t)bc * L_;
        float alo = 0.f, ahi = 0.f;
        #pragma unroll
        for (int k = 0; k < 8; k++){
            int o = l + k - 3;
            if (o < 0) o = -o;
            if (o >= L_) o = 2*L_ - 2 - o;
            float v = row[o];
            alo += v * filt[k];
            ahi += v * filt[8 + k];
        }
        apOut[i] = alo;
        stacked[(((size_t)bb*CS_ + chOff + c) << 11) + l] = ahi;
        if (copyX) stacked[(((size_t)bb*CS_ + c) << 11) + l] = row[l];
    }
}

// ---------------- fused ode_f core ----------------
// 4co x 2l accumulation from smem: x rows stride 64, w rows stride 192 (3k x 64co)
template<int NCI>
__device__ __forceinline__ void acc_run(const float* __restrict__ xsm,
                                        const float* __restrict__ wsm,
                                        int co0, int l0, ull acc[2][2]){
    #pragma unroll 8
    for (int ci = 0; ci < NCI; ci++){
        const float* xr = xsm + ci*64 + l0;
        float2 xa = *(const float2*)xr;
        float2 xb = *(const float2*)(xr + 2);
        ull q0 = bcast2(xa.x), q1 = bcast2(xa.y), q2 = bcast2(xb.x), q3 = bcast2(xb.y);
        const float* wr = wsm + ci*192 + co0;
        float4 w0 = *(const float4*)(wr);
        float4 w1 = *(const float4*)(wr + 64);
        float4 w2 = *(const float4*)(wr + 128);
        ull a0 = pk2(w0.x,w0.y), b0 = pk2(w0.z,w0.w);
        ull a1 = pk2(w1.x,w1.y), b1 = pk2(w1.z,w1.w);
        ull a2 = pk2(w2.x,w2.y), b2 = pk2(w2.z,w2.w);
        fma2(acc[0][0], a0, q0); fma2(acc[0][1], a0, q1);
        fma2(acc[1][0], b0, q0); fma2(acc[1][1], b0, q1);
        fma2(acc[0][0], a1, q1); fma2(acc[0][1], a1, q2);
        fma2(acc[1][0], b1, q1); fma2(acc[1][1], b1, q2);
        fma2(acc[0][0], a2, q2); fma2(acc[0][1], a2, q3);
        fma2(acc[1][0], b2, q2); fma2(acc[1][1], b2, q3);
    }
}

// grid (37, 8), 512 threads; warp = one co-group (ct = t>>5), lanes sweep l (2 per lane)
// slots: x 62 (gl = L0-3+j), h1 60 (gl = L0-2+i), h2 58 (gl = L0-1+i), out 56 (gl = L0+i)
template<int NA>
__global__ __launch_bounds__(512, 2)
void kfused(const float* __restrict__ y,
            const float* __restrict__ a1, float c1,
            const float* __restrict__ a2, float c2,
            const float* __restrict__ a3, float c3,
            const float* __restrict__ a4, float c4,
            const float* __restrict__ a5, float c5,
            const float* __restrict__ w1, const float* __restrict__ b1v,
            const float* __restrict__ w2, const float* __restrict__ b2v,
            const float* __restrict__ w3, const float* __restrict__ b3v,
            const float* __restrict__ gb, float* __restrict__ outp){
    extern __shared__ float sm[];
    const int t   = threadIdx.x;
    const int ct  = t >> 5;
    const int lane= t & 31;
    const int co0 = ct * 4;
    const int l0a = lane * 2;
    const int b   = blockIdx.y;
    const int L0  = blockIdx.x * LT_;

    const size_t inOff = (size_t)b * CS_ * L_;
    const float* yb = y + inOff;
    const float* p1 = (NA>=1) ? (a1 + inOff) : yb;
    const float* p2 = (NA>=2) ? (a2 + inOff) : yb;
    const float* p3 = (NA>=3) ? (a3 + inOff) : yb;
    const float* p4 = (NA>=4) ? (a4 + inOff) : yb;
    const float* p5 = (NA>=5) ? (a5 + inOff) : yb;

    // -------- stage 1: 8 ci-chunks, double-buffered --------
    ull acc1[2][2] = {{0ULL,0ULL},{0ULL,0ULL}};
    const int l1c = min(l0a, 58);

    auto loadX = [&](int c0, int buf){
        #pragma unroll
        for (int rr = 0; rr < 4; rr++){
            int idx = t + rr*512;
            int ci = idx >> 6, j = idx & 63;
            int gl = L0 - 3 + j;
            float v = 0.f;
            if (j < 62 && ((unsigned)gl < (unsigned)L_)){
                size_t o = (size_t)(c0 + ci) * L_ + (size_t)gl;
                v = yb[o];
                if (NA>=1) v = fmaf(c1, p1[o], v);
                if (NA>=2) v = fmaf(c2, p2[o], v);
                if (NA>=3) v = fmaf(c3, p3[o], v);
                if (NA>=4) v = fmaf(c4, p4[o], v);
                if (NA>=5) v = fmaf(c5, p5[o], v);
            }
            sm[XSO + (buf<<11) + idx] = v;
        }
    };
    auto loadW1 = [&](int c0, int half){
        #pragma unroll
        for (int rr = 0; rr < 12; rr++){
            int idx = t + rr*512;
            int co = idx & 63, r = idx >> 6;
            int ci = r / 3, k = r - ci*3;
            sm[WSO + half*6144 + ci*192 + k*64 + co] =
                w1[(size_t)co*(CS_*3) + (size_t)(c0+ci)*3 + k];
        }
    };

    loadX(0, 0); loadW1(0, 0);
    __syncthreads();
    #pragma unroll 1
    for (int c = 0; c < 8; c++){
        if (c < 7){ loadX((c+1)*32, (c+1)&1); loadW1((c+1)*32, (c+1)&1); }
        acc_run<32>(sm + XSO + ((c&1)<<11), sm + WSO + (c&1)*6144, co0, l1c, acc1);
        __syncthreads();
    }

    // epilogue 1: bias + FiLM + GELU, zero outside [0,L)
    {
        float2 ua = unpk(acc1[0][0]), ub = unpk(acc1[0][1]);
        float2 uc = unpk(acc1[1][0]), ud = unpk(acc1[1][1]);
        float v0[4] = {ua.x, ua.y, uc.x, uc.y};
        float v1[4] = {ub.x, ub.y, ud.x, ud.y};
        int gl0 = L0 - 2 + l1c;
        bool m0 = ((unsigned)gl0     < (unsigned)L_);
        bool m1 = ((unsigned)(gl0+1) < (unsigned)L_);
        if (lane < 30){
            #pragma unroll
            for (int cc = 0; cc < 4; cc++){
                int co = co0 + cc;
                float bia = b1v[co], ga = 1.f + gb[co], be = gb[64+co];
                float f0 = m0 ? gelu_f(ga*(v0[cc]+bia)+be) : 0.f;
                float f1 = m1 ? gelu_f(ga*(v1[cc]+bia)+be) : 0.f;
                *(float2*)&sm[H1O + co*64 + l1c] = make_float2(f0, f1);
            }
        }
    }
    // load w2 (full 64 ci)
    #pragma unroll
    for (int rr = 0; rr < 24; rr++){
        int idx = t + rr*512;
        int co = idx & 63, r = idx >> 6;
        int ci = r / 3, k = r - ci*3;
        sm[WSO + ci*192 + k*64 + co] = w2[(size_t)co*(HD_*3) + ci*3 + k];
    }
    __syncthreads();

    // -------- stage 2 --------
    {
        ull acc2[2][2] = {{0ULL,0ULL},{0ULL,0ULL}};
        const int l2c = min(l0a, 56);
        acc_run<64>(sm + H1O, sm + WSO, co0, l2c, acc2);
        float2 ua = unpk(acc2[0][0]), ub = unpk(acc2[0][1]);
        float2 uc = unpk(acc2[1][0]), ud = unpk(acc2[1][1]);
        float v0[4] = {ua.x, ua.y, uc.x, uc.y};
        float v1[4] = {ub.x, ub.y, ud.x, ud.y};
        int gl0 = L0 - 1 + l2c;
        bool m0 = ((unsigned)gl0     < (unsigned)L_);
        bool m1 = ((unsigned)(gl0+1) < (unsigned)L_);
        if (lane < 29){
            #pragma unroll
            for (int cc = 0; cc < 4; cc++){
                int co = co0 + cc;
                float bia = b2v[co];
                float f0 = m0 ? gelu_f(v0[cc]+bia) : 0.f;
                float f1 = m1 ? gelu_f(v1[cc]+bia) : 0.f;
                *(float2*)&sm[H2O + co*64 + l2c] = make_float2(f0, f1);
            }
        }
    }
    __syncthreads();

    // -------- stage 3: 4 co-groups of 64 --------
    const int l3c = min(l0a, 54);
    #pragma unroll 1
    for (int g = 0; g < 4; g++){
        #pragma unroll
        for (int rr = 0; rr < 24; rr++){
            int idx = t + rr*512;
            int co = idx & 63, r = idx >> 6;
            int ci = r / 3, k = r - ci*3;
            sm[WSO + ci*192 + k*64 + co] = w3[(size_t)(g*64+co)*(HD_*3) + ci*3 + k];
        }
        __syncthreads();
        ull acc3[2][2] = {{0ULL,0ULL},{0ULL,0ULL}};
        acc_run<64>(sm + H2O, sm + WSO, co0, l3c, acc3);
        int gl0 = L0 + l3c;
        if (lane < 28 && gl0 < L_){
            float2 ua = unpk(acc3[0][0]), ub = unpk(acc3[0][1]);
            float2 uc = unpk(acc3[1][0]), ud = unpk(acc3[1][1]);
            float v0[4] = {ua.x, ua.y, uc.x, uc.y};
            float v1[4] = {ub.x, ub.y, ud.x, ud.y};
            #pragma unroll
            for (int cc = 0; cc < 4; cc++){
                int co = g*64 + co0 + cc;
                float bia = b3v[co];
                *(float2*)&outp[((size_t)(b*CS_ + co))*L_ + gl0] =
                    make_float2(v0[cc]+bia, v1[cc]+bia);
            }
        }
        __syncthreads();
    }
}

// ---------------- stage combination (final y update), float4 ----------------
__global__ void kcomb(float* __restrict__ dst, const float* __restrict__ y,
                      const float* __restrict__ s1, float c1,
                      const float* __restrict__ s2, float c2,
                      const float* __restrict__ s3, float c3,
                      const float* __restrict__ s4, float c4,
                      const float* __restrict__ s5, float c5){
    int i = blockIdx.x*256 + threadIdx.x;
    float4 v = ((const float4*)y)[i];
    float4 t1 = ((const float4*)s1)[i];
    float4 t2 = ((const float4*)s2)[i];
    float4 t3 = ((const float4*)s3)[i];
    float4 t4 = ((const float4*)s4)[i];
    float4 t5 = ((const float4*)s5)[i];
    v.x += c1*t1.x + c2*t2.x + c3*t3.x + c4*t4.x + c5*t5.x;
    v.y += c1*t1.y + c2*t2.y + c3*t3.y + c4*t4.y + c5*t5.y;
    v.z += c1*t1.z + c2*t2.z + c3*t3.z + c4*t4.z + c5*t5.z;
    v.w += c1*t1.w + c2*t2.w + c3*t3.w + c4*t4.w + c5*t5.w;
    ((float4*)dst)[i] = v;
}

// ---------------- ecloss reduction ----------------
__global__ void kinner(const float* __restrict__ a, const float* __restrict__ d,
                       double* __restrict__ part){
    int bb = blockIdx.x, ch = blockIdx.y;
    size_t base = (size_t)bb*CS_*L_ + (size_t)ch*8192;
    double s = 0.0;
    for (int i = threadIdx.x; i < 8192; i += 256)
        s += (double)a[base+i] * (double)d[base+i];
    __shared__ double sm[256];
    sm[threadIdx.x] = s; __syncthreads();
    for (int st = 128; st > 0; st >>= 1){
        if (threadIdx.x < st) sm[threadIdx.x] += sm[threadIdx.x+st];
        __syncthreads();
    }
    if (threadIdx.x == 0) part[bb*64 + ch] = sm[0];
}

__global__ void kfinal(const double* __restrict__ part, float* __restrict__ out){
    if (threadIdx.x == 0){
        double acc = 0.0;
        for (int b = 0; b < 8; b++){
            double s = 0.0;
            for (int j = 0; j < 64; j++) s += part[b*64+j];
            acc += s*s;
        }
        out[4194304] = (float)(acc / 8.0);
    }
}

// ---------------- output permute ----------------
__global__ void kout(const float* __restrict__ y, float* __restrict__ out){
    int i = blockIdx.x*256 + threadIdx.x;
    int l = i & (L_-1); int bc = i >> 11; int c = bc & 255; int b = bc >> 8;
    int g = c >> 6; int cc = c & 63;
    out[(size_t)g*(B_*C_*L_) + (((size_t)b*C_ + cc) << 11) + l] = y[i];
}

// ---------------- host orchestration ----------------
extern "C" void kernel_launch(void* const* d_in, const int* in_sizes, int n_in,
                              void* d_out, int out_size){
    const float* x   = (const float*)d_in[0];
    const float* sw1 = (const float*)d_in[1];
    const float* sb1 = (const float*)d_in[2];
    const float* sw2 = (const float*)d_in[3];
    const float* sb2 = (const float*)d_in[4];
    const float* sw3 = (const float*)d_in[5];
    const float* sb3 = (const float*)d_in[6];
    const float* tw1 = (const float*)d_in[7];
    const float* tb1 = (const float*)d_in[8];
    const float* tw2 = (const float*)d_in[9];
    const float* tb2 = (const float*)d_in[10];
    const float* cw  = (const float*)d_in[11];
    const float* cb  = (const float*)d_in[12];
    const float* k1  = (const float*)d_in[13];
    const float* kb1 = (const float*)d_in[14];
    const float* k2  = (const float*)d_in[15];
    const float* kb2 = (const float*)d_in[16];
    const float* k3  = (const float*)d_in[17];
    const float* kb3 = (const float*)d_in[18];
    float* out = (float*)d_out;

    float *stacked, *y, *sbase, *apA, *apB, *amax, *gb;
    double* part;
    cudaGetSymbolAddress((void**)&stacked, g_stacked);
    cudaGetSymbolAddress((void**)&y,       g_y);
    cudaGetSymbolAddress((void**)&sbase,   g_s);
    cudaGetSymbolAddress((void**)&apA,     g_apA);
    cudaGetSymbolAddress((void**)&apB,     g_apB);
    cudaGetSymbolAddress((void**)&amax,    g_amax);
    cudaGetSymbolAddress((void**)&gb,      g_gb);
    cudaGetSymbolAddress((void**)&part,    g_part);

    cudaFuncSetAttribute(kfused<0>, cudaFuncAttributeMaxDynamicSharedMemorySize, SMB);
    cudaFuncSetAttribute(kfused<1>, cudaFuncAttributeMaxDynamicSharedMemorySize, SMB);
    cudaFuncSetAttribute(kfused<2>, cudaFuncAttributeMaxDynamicSharedMemorySize, SMB);
    cudaFuncSetAttribute(kfused<3>, cudaFuncAttributeMaxDynamicSharedMemorySize, SMB);
    cudaFuncSetAttribute(kfused<4>, cudaFuncAttributeMaxDynamicSharedMemorySize, SMB);
    cudaFuncSetAttribute(kfused<5>, cudaFuncAttributeMaxDynamicSharedMemorySize, SMB);

    float* S[6];
    for (int k = 0; k < 6; k++) S[k] = sbase + (size_t)k * NN_;

    // ---- prologue: gamma/beta + level-1 max in one kernel, then fused dywan+wavelet ----
    kprep<<<537, 256>>>(x, tw1, tb1, tw2, tb2, cw, cb, amax, gb);
    kwavF<<<1024, 256>>>(x,   amax, sw1, sb1, sw2, sb2, sw3, sb3, apA, stacked, 64,  1);
    kmax <<<512, 256>>>(apA, amax);
    kwavF<<<1024, 256>>>(apA, amax, sw1, sb1, sw2, sb2, sw3, sb3, apB, stacked, 128, 0);
    kmax <<<512, 256>>>(apB, amax);
    kwavF<<<1024, 256>>>(apB, amax, sw1, sb1, sw2, sb2, sw3, sb3, apA, stacked, 192, 0);
    cudaMemcpyAsync(y, stacked, (size_t)NN_ * sizeof(float), cudaMemcpyDeviceToDevice, 0);

    const dim3 gF(NBX_, B_);

    auto odef = [&](int ev, int na,
                    const float* a1, float c1, const float* a2, float c2,
                    const float* a3, float c3, const float* a4, float c4,
                    const float* a5, float c5, float* sout){
        const float* gbe = gb + ev*128;
        switch (na){
        case 0: kfused<0><<<gF,512,SMB>>>(y,a1,c1,a2,c2,a3,c3,a4,c4,a5,c5,k1,kb1,k2,kb2,k3,kb3,gbe,sout); break;
        case 1: kfused<1><<<gF,512,SMB>>>(y,a1,c1,a2,c2,a3,c3,a4,c4,a5,c5,k1,kb1,k2,kb2,k3,kb3,gbe,sout); break;
        case 2: kfused<2><<<gF,512,SMB>>>(y,a1,c1,a2,c2,a3,c3,a4,c4,a5,c5,k1,kb1,k2,kb2,k3,kb3,gbe,sout); break;
        case 3: kfused<3><<<gF,512,SMB>>>(y,a1,c1,a2,c2,a3,c3,a4,c4,a5,c5,k1,kb1,k2,kb2,k3,kb3,gbe,sout); break;
        case 4: kfused<4><<<gF,512,SMB>>>(y,a1,c1,a2,c2,a3,c3,a4,c4,a5,c5,k1,kb1,k2,kb2,k3,kb3,gbe,sout); break;
        default:kfused<5><<<gF,512,SMB>>>(y,a1,c1,a2,c2,a3,c3,a4,c4,a5,c5,k1,kb1,k2,kb2,k3,kb3,gbe,sout); break;
        }
    };

    const double hs = 0.25;
    const float* Z = nullptr;
    for (int st = 0; st < 4; st++){
        int e = st*6;
        odef(e+0, 0, Z,0,Z,0,Z,0,Z,0,Z,0, S[0]);
        odef(e+1, 1, S[0],(float)(hs*1.0/5.0), Z,0,Z,0,Z,0,Z,0, S[1]);
        odef(e+2, 2, S[0],(float)(hs*3.0/40.0), S[1],(float)(hs*9.0/40.0), Z,0,Z,0,Z,0, S[2]);
        odef(e+3, 3, S[0],(float)(hs*44.0/45.0), S[1],(float)(-hs*56.0/15.0),
                  S[2],(float)(hs*32.0/9.0), Z,0,Z,0, S[3]);
        odef(e+4, 4, S[0],(float)(hs*19372.0/6561.0), S[1],(float)(-hs*25360.0/2187.0),
                  S[2],(float)(hs*64448.0/6561.0), S[3],(float)(-hs*212.0/729.0), Z,0, S[4]);
        odef(e+5, 5, S[0],(float)(hs*9017.0/3168.0), S[1],(float)(-hs*355.0/33.0),
                  S[2],(float)(hs*46732.0/5247.0), S[3],(float)(hs*49.0/176.0),
                  S[4],(float)(-hs*5103.0/18656.0), S[5]);
        kcomb<<<NN_/1024,256>>>(y, y, S[0],(float)(hs*35.0/384.0), S[2],(float)(hs*500.0/1113.0),
                          S[3],(float)(hs*125.0/192.0), S[4],(float)(-hs*2187.0/6784.0),
                          S[5],(float)(hs*11.0/84.0));
    }

    // ---- dx = ode_f(1.0, ode_out) ; ecloss ----
    odef(24, 0, Z,0,Z,0,Z,0,Z,0,Z,0, S[0]);
    kinner<<<dim3(B_, 64), 256>>>(stacked, S[0], part);

    // ---- outputs ----
    kout<<<NN_/256, 256>>>(y, out);
    kfinal<<<1, 32>>>(part, out);
}

// round 7
// speedup vs baseline: 1.1816x; 1.0444x over previous
#include <cuda_runtime.h>
#include <math.h>

#define B_ 8
#define C_ 64
#define L_ 2048
#define CS_ 256
#define HD_ 64
#define NN_ (B_*CS_*L_)      // 4194304
#define NC_ (B_*C_*L_)       // 1048576
#define NEVAL_ 25
#define LT_ 56               // l-tile per block
#define NBX_ 37              // 37*56 = 2072 >= 2048

// smem float offsets for kfused
#define XSO 0                // xs: 2 buffers x 32ci x 64 slots = 4096 floats
#define H1O 4096             // h1: 64co x 64 slots
#define H2O 8192             // h2: 64co x 64 slots
#define WSO 12288            // ws (as ull pairs): 64ci x 3k x 32p = 6144 ull = 12288 floats
#define SM_FLOATS 24576
#define SMB (SM_FLOATS*4)    // 98304 bytes

// ---------------- scratch (device globals; no runtime allocation) ----------------
__device__ float g_stacked[NN_];
__device__ float g_y[NN_];
__device__ float g_y2[NN_];
__device__ float g_s[6][NN_];
__device__ float g_apA[NC_];
__device__ float g_apB[NC_];
__device__ float g_amax[B_*C_];
__device__ float g_filt[16];
__device__ float g_gb[NEVAL_*128];
__device__ double g_part[B_*64];
__device__ int   g_ctr = 0;

typedef unsigned long long ull;

__device__ __forceinline__ float gelu_f(float x){
    return 0.5f * x * (1.0f + erff(x * 0.70710678118654752440f));
}
__device__ __forceinline__ ull bcast2(float x){
    ull r; asm("mov.b64 %0, {%1, %1};" : "=l"(r) : "f"(x)); return r;
}
__device__ __forceinline__ ull pk2(float a, float b){
    ull r; asm("mov.b64 %0, {%1, %2};" : "=l"(r) : "f"(a), "f"(b)); return r;
}
__device__ __forceinline__ void fma2(ull &d, ull a, ull b){
    asm("fma.rn.f32x2 %0, %1, %2, %0;" : "+l"(d) : "l"(a), "l"(b));
}
__device__ __forceinline__ float2 unpk(ull v){
    float lo, hi; asm("mov.b64 {%0, %1}, %2;" : "=f"(lo), "=f"(hi) : "l"(v));
    return make_float2(lo, hi);
}

// ---------------- dywan MLP tail (whole block, 256 threads) ----------------
__device__ void dywan_tail(const float* __restrict__ amax,
                           const float* __restrict__ sw1, const float* __restrict__ sb1,
                           const float* __restrict__ sw2, const float* __restrict__ sb2,
                           const float* __restrict__ sw3, const float* __restrict__ sb3,
                           float* __restrict__ filtOut){
    __shared__ float feat[256], g2s[256], raw[128], nrm[16];
    int t = threadIdx.x;
    { int bb = t >> 5, h = t & 31;
      float s = sb1[h];
      const float* am = amax + bb*64; const float* w = sw1 + h*64;
      #pragma unroll 8
      for (int c = 0; c < 64; c++) s += am[c]*w[c];
      feat[t] = gelu_f(s); }
    __syncthreads();
    { int bb = t >> 5, h = t & 31;
      float s = sb2[h];
      #pragma unroll 8
      for (int k = 0; k < 32; k++) s += feat[bb*32+k]*sw2[h*32+k];
      g2s[t] = gelu_f(s); }
    __syncthreads();
    if (t < 128){ int bb = t >> 4, j = t & 15;
      float s = sb3[j];
      #pragma unroll 8
      for (int k = 0; k < 32; k++) s += g2s[bb*32+k]*sw3[j*32+k];
      raw[t] = s; }
    __syncthreads();
    if (t < 16){ int bb = t >> 1, hh = t & 1;
      float s = 0.f;
      for (int j = 0; j < 8; j++){ float v = raw[bb*16 + hh*8 + j]; s += v*v; }
      nrm[t] = sqrtf(s); }
    __syncthreads();
    if (t < 16){ int hh = t >> 3, j = t & 7;
      float s = 0.f;
      for (int bb = 0; bb < 8; bb++) s += raw[bb*16 + hh*8 + j] / nrm[bb*2 + hh];
      filtOut[hh*8 + j] = s * 0.125f; }
}

// ---------------- kprep: amax(x) rows 0-511, gb blocks 512-536, dywan level1 block 537 ----------------
__global__ void kprep(const float* __restrict__ x,
                      const float* __restrict__ tw1, const float* __restrict__ tb1,
                      const float* __restrict__ tw2, const float* __restrict__ tb2,
                      const float* __restrict__ cw,  const float* __restrict__ cb,
                      const float* __restrict__ sw1, const float* __restrict__ sb1,
                      const float* __restrict__ sw2, const float* __restrict__ sb2,
                      const float* __restrict__ sw3, const float* __restrict__ sb3,
                      float* __restrict__ amax, float* __restrict__ gbout,
                      float* __restrict__ filt, int* __restrict__ ctr){
    int t = threadIdx.x;
    if (blockIdx.x < 512){
        int row = blockIdx.x;
        const float* p = x + (size_t)row * L_;
        float m = -3.4e38f;
        for (int i = t; i < L_; i += 256) m = fmaxf(m, p[i]);
        __shared__ float sm[256];
        sm[t] = m; __syncthreads();
        for (int s = 128; s > 0; s >>= 1){
            if (t < s) sm[t] = fmaxf(sm[t], sm[t+s]);
            __syncthreads();
        }
        if (t == 0){
            amax[row] = sm[0];
            __threadfence();
            atomicAdd(ctr, 1);
        }
    } else if (blockIdx.x < 537){
        int e = blockIdx.x - 512;
        const double hs = 0.25;
        double td;
        if (e == 24) td = 1.0;
        else {
            int i = e / 6, s = e % 6;
            double off;
            switch (s){
                case 0: off = 0.0; break;
                case 1: off = hs/5.0; break;
                case 2: off = 3.0*hs/10.0; break;
                case 3: off = 4.0*hs/5.0; break;
                case 4: off = 8.0*hs/9.0; break;
                default: off = hs; break;
            }
            td = (double)i*hs + off;
        }
        float tt = (float)td;
        __shared__ float te1[16], te2[16];
        if (t < 16) te1[t] = gelu_f(tt * tw1[t] + tb1[t]);
        __syncthreads();
        if (t < 16){
            float s = tb2[t];
            #pragma unroll
            for (int k = 0; k < 16; k++) s += te1[k]*tw2[t*16+k];
            te2[t] = s;
        }
        __syncthreads();
        if (t < 128){
            float s = cb[t];
            #pragma unroll
            for (int k = 0; k < 16; k++) s += te2[k]*cw[t*16+k];
            gbout[e*128 + t] = s;
        }
    } else {
        // wait for all amax rows, then dywan for level 1
        if (t == 0){
            while (atomicAdd(ctr, 0) < 512) __nanosleep(200);
        }
        __syncthreads();
        __threadfence();
        dywan_tail(amax, sw1, sb1, sw2, sb2, sw3, sb3, filt);
        __syncthreads();
        if (t == 0) atomicExch(ctr, 0);
    }
}

// ---------------- kwavF: per-row wavelet conv + row-max of approx + optional next-level dywan ----------------
// grid 512 (one block per (b,c) row), 256 threads, 8 outputs/thread
__global__ void kwavF(const float* __restrict__ src,
                      const float* __restrict__ filtIn,
                      float* __restrict__ apOut, float* __restrict__ stacked,
                      float* __restrict__ amaxNext, int chOff, int copyX, int computeNext,
                      const float* __restrict__ sw1, const float* __restrict__ sb1,
                      const float* __restrict__ sw2, const float* __restrict__ sb2,
                      const float* __restrict__ sw3, const float* __restrict__ sb3,
                      float* __restrict__ filtOut, int* __restrict__ ctr){
    __shared__ float xr[2064];
    __shared__ float red[256];
    __shared__ int lastFlag;
    int t = threadIdx.x;
    int r = blockIdx.x;
    int b = r >> 6, c = r & 63;
    const float* row = src + (size_t)r * L_;

    float f[16];
    #pragma unroll
    for (int i = 0; i < 16; i++) f[i] = filtIn[i];

    // stage row with reflect pad: xr[s] = x[reflect(s-3)], s in [0, 2056)
    for (int s = t; s < 2056; s += 256){
        int gl = s - 3;
        if (gl < 0) gl = -gl;
        if (gl >= L_) gl = 2*L_ - 2 - gl;
        xr[s] = row[gl];
    }
    __syncthreads();

    int l0 = t * 8;
    float xv[16];
    #pragma unroll
    for (int i = 0; i < 4; i++)
        *(float4*)&xv[i*4] = *(const float4*)&xr[l0 + i*4];

    float alo[8], ahi[8];
    float mlo = -3.4e38f;
    #pragma unroll
    for (int j = 0; j < 8; j++){
        float a = 0.f, h = 0.f;
        #pragma unroll
        for (int k = 0; k < 8; k++){
            float v = (j + k < 15) ? xv[j+k] : xr[l0 + j + k];
            a += v * f[k];
            h += v * f[8+k];
        }
        alo[j] = a; ahi[j] = h;
        mlo = fmaxf(mlo, a);
    }
    // writes
    *(float4*)&apOut[(size_t)r*L_ + l0]     = *(float4*)&alo[0];
    *(float4*)&apOut[(size_t)r*L_ + l0 + 4] = *(float4*)&alo[4];
    float* st = stacked + (((size_t)b*CS_ + chOff + c) << 11) + l0;
    *(float4*)&st[0] = *(float4*)&ahi[0];
    *(float4*)&st[4] = *(float4*)&ahi[4];
    if (copyX){
        float* sx = stacked + (((size_t)b*CS_ + c) << 11) + l0;
        #pragma unroll
        for (int j = 0; j < 8; j++) sx[j] = xr[l0 + 3 + j];
    }
    // row max reduce
    red[t] = mlo; __syncthreads();
    for (int s = 128; s > 0; s >>= 1){
        if (t < s) red[t] = fmaxf(red[t], red[t+s]);
        __syncthreads();
    }
    if (t == 0) amaxNext[r] = red[0];

    if (computeNext){
        __syncthreads();
        if (t == 0){
            __threadfence();
            int old = atomicAdd(ctr, 1);
            lastFlag = (old == 511) ? 1 : 0;
        }
        __syncthreads();
        if (lastFlag){
            __threadfence();
            dywan_tail(amaxNext, sw1, sb1, sw2, sb2, sw3, sb3, filtOut);
            __syncthreads();
            if (t == 0) atomicExch(ctr, 0);
        }
    }
}

// ---------------- fused ode_f core ----------------
// 4co x 2l accumulation; x rows stride 64 (float), w as ull pairs stride 96/ci
template<int NCI>
__device__ __forceinline__ void acc_run(const float* __restrict__ xsm,
                                        const ull* __restrict__ wsp,
                                        int cp0, int l0, ull acc[2][2]){
    #pragma unroll 8
    for (int ci = 0; ci < NCI; ci++){
        const float* xr = xsm + ci*64 + l0;
        float2 xa = *(const float2*)xr;
        float2 xb = *(const float2*)(xr + 2);
        ull q0 = bcast2(xa.x), q1 = bcast2(xa.y), q2 = bcast2(xb.x), q3 = bcast2(xb.y);
        const ull* wr = wsp + ci*96 + cp0;
        ulonglong2 w0 = *(const ulonglong2*)(wr);
        ulonglong2 w1 = *(const ulonglong2*)(wr + 32);
        ulonglong2 w2 = *(const ulonglong2*)(wr + 64);
        fma2(acc[0][0], w0.x, q0); fma2(acc[0][1], w0.x, q1);
        fma2(acc[1][0], w0.y, q0); fma2(acc[1][1], w0.y, q1);
        fma2(acc[0][0], w1.x, q1); fma2(acc[0][1], w1.x, q2);
        fma2(acc[1][0], w1.y, q1); fma2(acc[1][1], w1.y, q2);
        fma2(acc[0][0], w2.x, q2); fma2(acc[0][1], w2.x, q3);
        fma2(acc[1][0], w2.y, q2); fma2(acc[1][1], w2.y, q3);
    }
}

// grid (37, 8), 512 threads; warp = co-group (ct=t>>5), lanes sweep l (2 per lane)
// slots: x 62 (gl=L0-3+j), h1 60 (gl=L0-2+i), h2 58 (gl=L0-1+i), out 56 (gl=L0+i)
template<int NA, bool YC>
__global__ __launch_bounds__(512, 2)
void kfused(const float* __restrict__ y,
            const float* __restrict__ a1, float c1,
            const float* __restrict__ a2, float c2,
            const float* __restrict__ a3, float c3,
            const float* __restrict__ a4, float c4,
            const float* __restrict__ a5, float c5,
            const float* __restrict__ w1, const float* __restrict__ b1v,
            const float* __restrict__ w2, const float* __restrict__ b2v,
            const float* __restrict__ w3, const float* __restrict__ b3v,
            const float* __restrict__ gb,
            float* __restrict__ youtg, float* __restrict__ outp){
    extern __shared__ float sm[];
    ull* wsp = (ull*)(sm + WSO);
    const int t   = threadIdx.x;
    const int ct  = t >> 5;
    const int lane= t & 31;
    const int co0 = ct * 4;
    const int cp0 = ct * 2;
    const int l0a = lane * 2;
    const int b   = blockIdx.y;
    const int L0  = blockIdx.x * LT_;

    const size_t inOff = (size_t)b * CS_ * L_;
    const float* yb = y + inOff;
    const float* p1 = (NA>=1) ? (a1 + inOff) : yb;
    const float* p2 = (NA>=2) ? (a2 + inOff) : yb;
    const float* p3 = (NA>=3) ? (a3 + inOff) : yb;
    const float* p4 = (NA>=4) ? (a4 + inOff) : yb;
    const float* p5 = (NA>=5) ? (a5 + inOff) : yb;
    float* youtb = YC ? (youtg + inOff) : nullptr;

    // -------- stage 1: 8 ci-chunks, double-buffered --------
    ull acc1[2][2] = {{0ULL,0ULL},{0ULL,0ULL}};
    const int l1c = min(l0a, 58);

    auto loadX = [&](int c0, int buf){
        #pragma unroll
        for (int rr = 0; rr < 4; rr++){
            int idx = t + rr*512;
            int ci = idx >> 6, j = idx & 63;
            int gl = L0 - 3 + j;
            float v = 0.f;
            if (j < 62 && ((unsigned)gl < (unsigned)L_)){
                size_t o = (size_t)(c0 + ci) * L_ + (size_t)gl;
                v = yb[o];
                if (NA>=1) v = fmaf(c1, p1[o], v);
                if (NA>=2) v = fmaf(c2, p2[o], v);
                if (NA>=3) v = fmaf(c3, p3[o], v);
                if (NA>=4) v = fmaf(c4, p4[o], v);
                if (NA>=5) v = fmaf(c5, p5[o], v);
                if (YC){ if (j >= 3 && j < 59) youtb[o] = v; }
            }
            sm[XSO + (buf<<11) + idx] = v;
        }
    };
    auto loadW1 = [&](int c0, int half){
        #pragma unroll
        for (int rr = 0; rr < 6; rr++){
            int idx = t + rr*512;     // 3072 pair slots
            int p = idx & 31; int r = idx >> 5;
            int ci = r / 3, k = r - ci*3;
            const float* wbase = w1 + (size_t)(c0+ci)*3 + k;
            float wa = wbase[(size_t)(2*p)  *(CS_*3)];
            float wb = wbase[(size_t)(2*p+1)*(CS_*3)];
            wsp[half*3072 + ci*96 + k*32 + p] = pk2(wa, wb);
        }
    };

    loadX(0, 0); loadW1(0, 0);
    __syncthreads();
    #pragma unroll 1
    for (int c = 0; c < 8; c++){
        if (c < 7){ loadX((c+1)*32, (c+1)&1); loadW1((c+1)*32, (c+1)&1); }
        acc_run<32>(sm + XSO + ((c&1)<<11), wsp + (c&1)*3072, cp0, l1c, acc1);
        __syncthreads();
    }

    // epilogue 1: bias + FiLM + GELU; zero outside [0,L)
    {
        float2 ua = unpk(acc1[0][0]), ub = unpk(acc1[0][1]);
        float2 uc = unpk(acc1[1][0]), ud = unpk(acc1[1][1]);
        float v0[4] = {ua.x, ua.y, uc.x, uc.y};
        float v1[4] = {ub.x, ub.y, ud.x, ud.y};
        int gl0 = L0 - 2 + l1c;
        bool m0 = ((unsigned)gl0     < (unsigned)L_);
        bool m1 = ((unsigned)(gl0+1) < (unsigned)L_);
        if (lane < 30){
            #pragma unroll
            for (int cc = 0; cc < 4; cc++){
                int co = co0 + cc;
                float bia = b1v[co], ga = 1.f + gb[co], be = gb[64+co];
                float f0 = m0 ? gelu_f(ga*(v0[cc]+bia)+be) : 0.f;
                float f1 = m1 ? gelu_f(ga*(v1[cc]+bia)+be) : 0.f;
                *(float2*)&sm[H1O + co*64 + l1c] = make_float2(f0, f1);
            }
        }
    }
    // load w2 packed (full 64 ci): 6144 pair slots
    #pragma unroll
    for (int rr = 0; rr < 12; rr++){
        int idx = t + rr*512;
        int p = idx & 31; int r = idx >> 5;
        int ci = r / 3, k = r - ci*3;
        const float* wbase = w2 + (size_t)ci*3 + k;
        float wa = wbase[(size_t)(2*p)  *(HD_*3)];
        float wb = wbase[(size_t)(2*p+1)*(HD_*3)];
        wsp[ci*96 + k*32 + p] = pk2(wa, wb);
    }
    __syncthreads();

    // -------- stage 2 --------
    {
        ull acc2[2][2] = {{0ULL,0ULL},{0ULL,0ULL}};
        const int l2c = min(l0a, 56);
        acc_run<64>(sm + H1O, wsp, cp0, l2c, acc2);
        float2 ua = unpk(acc2[0][0]), ub = unpk(acc2[0][1]);
        float2 uc = unpk(acc2[1][0]), ud = unpk(acc2[1][1]);
        float v0[4] = {ua.x, ua.y, uc.x, uc.y};
        float v1[4] = {ub.x, ub.y, ud.x, ud.y};
        int gl0 = L0 - 1 + l2c;
        bool m0 = ((unsigned)gl0     < (unsigned)L_);
        bool m1 = ((unsigned)(gl0+1) < (unsigned)L_);
        if (lane < 29){
            #pragma unroll
            for (int cc = 0; cc < 4; cc++){
                int co = co0 + cc;
                float bia = b2v[co];
                float f0 = m0 ? gelu_f(v0[cc]+bia) : 0.f;
                float f1 = m1 ? gelu_f(v1[cc]+bia) : 0.f;
                *(float2*)&sm[H2O + co*64 + l2c] = make_float2(f0, f1);
            }
        }
    }
    __syncthreads();

    // -------- stage 3: 4 co-groups of 64 --------
    const int l3c = min(l0a, 54);
    #pragma unroll 1
    for (int g = 0; g < 4; g++){
        #pragma unroll
        for (int rr = 0; rr < 12; rr++){
            int idx = t + rr*512;
            int p = idx & 31; int r = idx >> 5;
            int ci = r / 3, k = r - ci*3;
            const float* wbase = w3 + (size_t)(g*64)*(HD_*3) + (size_t)ci*3 + k;
            float wa = wbase[(size_t)(2*p)  *(HD_*3)];
            float wb = wbase[(size_t)(2*p+1)*(HD_*3)];
            wsp[ci*96 + k*32 + p] = pk2(wa, wb);
        }
        __syncthreads();
        ull acc3[2][2] = {{0ULL,0ULL},{0ULL,0ULL}};
        acc_run<64>(sm + H2O, wsp, cp0, l3c, acc3);
        int gl0 = L0 + l3c;
        if (lane < 28 && gl0 < L_){
            float2 ua = unpk(acc3[0][0]), ub = unpk(acc3[0][1]);
            float2 uc = unpk(acc3[1][0]), ud = unpk(acc3[1][1]);
            float v0[4] = {ua.x, ua.y, uc.x, uc.y};
            float v1[4] = {ub.x, ub.y, ud.x, ud.y};
            #pragma unroll
            for (int cc = 0; cc < 4; cc++){
                int co = g*64 + co0 + cc;
                float bia = b3v[co];
                *(float2*)&outp[((size_t)(b*CS_ + co))*L_ + gl0] =
                    make_float2(v0[cc]+bia, v1[cc]+bia);
            }
        }
        __syncthreads();
    }
}

// ---------------- ecloss reduction ----------------
__global__ void kinner(const float* __restrict__ a, const float* __restrict__ d,
                       double* __restrict__ part){
    int bb = blockIdx.x, ch = blockIdx.y;
    size_t base = (size_t)bb*CS_*L_ + (size_t)ch*8192;
    double s = 0.0;
    for (int i = threadIdx.x; i < 8192; i += 256)
        s += (double)a[base+i] * (double)d[base+i];
    __shared__ double sm[256];
    sm[threadIdx.x] = s; __syncthreads();
    for (int st = 128; st > 0; st >>= 1){
        if (threadIdx.x < st) sm[threadIdx.x] += sm[threadIdx.x+st];
        __syncthreads();
    }
    if (threadIdx.x == 0) part[bb*64 + ch] = sm[0];
}

__global__ void kfinal(const double* __restrict__ part, float* __restrict__ out){
    if (threadIdx.x == 0){
        double acc = 0.0;
        for (int b = 0; b < 8; b++){
            double s = 0.0;
            for (int j = 0; j < 64; j++) s += part[b*64+j];
            acc += s*s;
        }
        out[4194304] = (float)(acc / 8.0);
    }
}

// ---------------- output permute ----------------
__global__ void kout(const float* __restrict__ y, float* __restrict__ out){
    int i = blockIdx.x*256 + threadIdx.x;
    int l = i & (L_-1); int bc = i >> 11; int c = bc & 255; int b = bc >> 8;
    int g = c >> 6; int cc = c & 63;
    out[(size_t)g*(B_*C_*L_) + (((size_t)b*C_ + cc) << 11) + l] = y[i];
}

// ---------------- host orchestration ----------------
extern "C" void kernel_launch(void* const* d_in, const int* in_sizes, int n_in,
                              void* d_out, int out_size){
    const float* x   = (const float*)d_in[0];
    const float* sw1 = (const float*)d_in[1];
    const float* sb1 = (const float*)d_in[2];
    const float* sw2 = (const float*)d_in[3];
    const float* sb2 = (const float*)d_in[4];
    const float* sw3 = (const float*)d_in[5];
    const float* sb3 = (const float*)d_in[6];
    const float* tw1 = (const float*)d_in[7];
    const float* tb1 = (const float*)d_in[8];
    const float* tw2 = (const float*)d_in[9];
    const float* tb2 = (const float*)d_in[10];
    const float* cw  = (const float*)d_in[11];
    const float* cb  = (const float*)d_in[12];
    const float* k1  = (const float*)d_in[13];
    const float* kb1 = (const float*)d_in[14];
    const float* k2  = (const float*)d_in[15];
    const float* kb2 = (const float*)d_in[16];
    const float* k3  = (const float*)d_in[17];
    const float* kb3 = (const float*)d_in[18];
    float* out = (float*)d_out;

    float *stacked, *y, *y2, *sbase, *apA, *apB, *amax, *filt, *gb;
    double* part; int* ctr;
    cudaGetSymbolAddress((void**)&stacked, g_stacked);
    cudaGetSymbolAddress((void**)&y,       g_y);
    cudaGetSymbolAddress((void**)&y2,      g_y2);
    cudaGetSymbolAddress((void**)&sbase,   g_s);
    cudaGetSymbolAddress((void**)&apA,     g_apA);
    cudaGetSymbolAddress((void**)&apB,     g_apB);
    cudaGetSymbolAddress((void**)&amax,    g_amax);
    cudaGetSymbolAddress((void**)&filt,    g_filt);
    cudaGetSymbolAddress((void**)&gb,      g_gb);
    cudaGetSymbolAddress((void**)&part,    g_part);
    cudaGetSymbolAddress((void**)&ctr,     g_ctr);

    cudaFuncSetAttribute(kfused<0,false>, cudaFuncAttributeMaxDynamicSharedMemorySize, SMB);
    cudaFuncSetAttribute(kfused<1,false>, cudaFuncAttributeMaxDynamicSharedMemorySize, SMB);
    cudaFuncSetAttribute(kfused<2,false>, cudaFuncAttributeMaxDynamicSharedMemorySize, SMB);
    cudaFuncSetAttribute(kfused<3,false>, cudaFuncAttributeMaxDynamicSharedMemorySize, SMB);
    cudaFuncSetAttribute(kfused<4,false>, cudaFuncAttributeMaxDynamicSharedMemorySize, SMB);
    cudaFuncSetAttribute(kfused<5,false>, cudaFuncAttributeMaxDynamicSharedMemorySize, SMB);
    cudaFuncSetAttribute(kfused<5,true >, cudaFuncAttributeMaxDynamicSharedMemorySize, SMB);

    float* S[6];
    for (int k = 0; k < 6; k++) S[k] = sbase + (size_t)k * NN_;

    // ---- prologue: 4 kernel launches total ----
    kprep<<<538, 256>>>(x, tw1, tb1, tw2, tb2, cw, cb,
                        sw1, sb1, sw2, sb2, sw3, sb3, amax, gb, filt, ctr);
    kwavF<<<512, 256>>>(x,   filt, apA, stacked, amax, 64,  1, 1,
                        sw1, sb1, sw2, sb2, sw3, sb3, filt, ctr);
    kwavF<<<512, 256>>>(apA, filt, apB, stacked, amax, 128, 0, 1,
                        sw1, sb1, sw2, sb2, sw3, sb3, filt, ctr);
    kwavF<<<512, 256>>>(apB, filt, apA, stacked, amax, 192, 0, 0,
                        sw1, sb1, sw2, sb2, sw3, sb3, filt, ctr);

    const dim3 gF(NBX_, B_);
    const double hs = 0.25;
    const float* Z = nullptr;

    auto ev_plain = [&](int ev, int na, const float* ybase,
                        const float* a1, float c1, const float* a2, float c2,
                        const float* a3, float c3, const float* a4, float c4,
                        const float* a5, float c5, float* sout){
        const float* gbe = gb + ev*128;
        switch (na){
        case 0: kfused<0,false><<<gF,512,SMB>>>(ybase,a1,c1,a2,c2,a3,c3,a4,c4,a5,c5,k1,kb1,k2,kb2,k3,kb3,gbe,nullptr,sout); break;
        case 1: kfused<1,false><<<gF,512,SMB>>>(ybase,a1,c1,a2,c2,a3,c3,a4,c4,a5,c5,k1,kb1,k2,kb2,k3,kb3,gbe,nullptr,sout); break;
        case 2: kfused<2,false><<<gF,512,SMB>>>(ybase,a1,c1,a2,c2,a3,c3,a4,c4,a5,c5,k1,kb1,k2,kb2,k3,kb3,gbe,nullptr,sout); break;
        case 3: kfused<3,false><<<gF,512,SMB>>>(ybase,a1,c1,a2,c2,a3,c3,a4,c4,a5,c5,k1,kb1,k2,kb2,k3,kb3,gbe,nullptr,sout); break;
        case 4: kfused<4,false><<<gF,512,SMB>>>(ybase,a1,c1,a2,c2,a3,c3,a4,c4,a5,c5,k1,kb1,k2,kb2,k3,kb3,gbe,nullptr,sout); break;
        default:kfused<5,false><<<gF,512,SMB>>>(ybase,a1,c1,a2,c2,a3,c3,a4,c4,a5,c5,k1,kb1,k2,kb2,k3,kb3,gbe,nullptr,sout); break;
        }
    };
    auto ev_ycomb = [&](int ev, const float* ybase, float** M, float* yout, float* sout){
        // combine coeffs: b-weights on (s1, s3, s4, s5, s6) = (M[0],M[2],M[3],M[4],M[5])
        kfused<5,true><<<gF,512,SMB>>>(ybase,
            M[0],(float)(hs*35.0/384.0), M[2],(float)(hs*500.0/1113.0),
            M[3],(float)(hs*125.0/192.0), M[4],(float)(-hs*2187.0/6784.0),
            M[5],(float)(hs*11.0/84.0),
            k1,kb1,k2,kb2,k3,kb3, gb + ev*128, yout, sout);
    };

    // stage-buffer mappings: A for steps 0,2; B for steps 1,3
    float* MA[6] = {S[0],S[1],S[2],S[3],S[4],S[5]};
    float* MB[6] = {S[1],S[0],S[2],S[3],S[4],S[5]};

    // within-step evals s2..s6 given mapping M and base yb
    auto step_tail = [&](int e, const float* ybase, float** M){
        ev_plain(e+1, 1, ybase, M[0],(float)(hs*1.0/5.0), Z,0,Z,0,Z,0,Z,0, M[1]);
        ev_plain(e+2, 2, ybase, M[0],(float)(hs*3.0/40.0), M[1],(float)(hs*9.0/40.0), Z,0,Z,0,Z,0, M[2]);
        ev_plain(e+3, 3, ybase, M[0],(float)(hs*44.0/45.0), M[1],(float)(-hs*56.0/15.0),
                 M[2],(float)(hs*32.0/9.0), Z,0,Z,0, M[3]);
        ev_plain(e+4, 4, ybase, M[0],(float)(hs*19372.0/6561.0), M[1],(float)(-hs*25360.0/2187.0),
                 M[2],(float)(hs*64448.0/6561.0), M[3],(float)(-hs*212.0/729.0), Z,0, M[4]);
        ev_plain(e+5, 5, ybase, M[0],(float)(hs*9017.0/3168.0), M[1],(float)(-hs*355.0/33.0),
                 M[2],(float)(hs*46732.0/5247.0), M[3],(float)(hs*49.0/176.0),
                 M[4],(float)(-hs*5103.0/18656.0), M[5]);
    };

    // step 0: base = stacked, mapping A, s1 plain
    ev_plain(0, 0, stacked, Z,0,Z,0,Z,0,Z,0,Z,0, MA[0]);
    step_tail(0, stacked, MA);
    // step 1: ycomb (stacked -> y), writes s1 into MB[0]=S1, mapping B
    ev_ycomb(6, stacked, MA, y, MB[0]);
    step_tail(6, y, MB);
    // step 2: ycomb (y -> y2), writes s1 into MA[0]=S0, mapping A
    ev_ycomb(12, y, MB, y2, MA[0]);
    step_tail(12, y2, MA);
    // step 3: ycomb (y2 -> y), mapping B
    ev_ycomb(18, y2, MA, y, MB[0]);
    step_tail(18, y, MB);
    // eval 24: ycomb (y -> y2 = ode_out), dx into S0
    ev_ycomb(24, y, MB, y2, S[0]);

    kinner<<<dim3(B_, 64), 256>>>(stacked, S[0], part);
    kout<<<NN_/256, 256>>>(y2, out);
    kfinal<<<1, 32>>>(part, out);
}

// round 9
// speedup vs baseline: 2.6202x; 2.2175x over previous
#include <cuda_runtime.h>
#include <math.h>

#define B_ 8
#define C_ 64
#define L_ 2048
#define CS_ 256
#define HD_ 64
#define NN_ (B_*CS_*L_)      // 4194304
#define NC_ (B_*C_*L_)       // 1048576
#define NEVAL_ 25
#define LT_ 56               // l-tile per block
#define NBX_ 37              // 37*56 = 2072 >= 2048

// smem float offsets for kfused
#define XSO 0                // xs: 2 buffers x 32ci x 64 slots = 4096 floats
#define H1O 4096             // h1: 64co x 64 slots
#define H2O 8192             // h2: 64co x 64 slots
#define WSO 12288            // ws (ull pairs): 64ci x 3k x 32p = 6144 ull = 12288 floats
#define SM_FLOATS 24576
#define SMB (SM_FLOATS*4)    // 98304 bytes

// packed weight offsets (ull units)
#define W1P 0                // 256ci x 3k x 32p = 24576
#define W2P 24576            // 64ci x 3k x 32p = 6144
#define W3P 30720            // 4g x 64ci x 3k x 32p = 24576
#define WPTOT 55296

// ---------------- scratch (device globals; no runtime allocation) ----------------
typedef unsigned long long ull;

__device__ float g_stacked[NN_];
__device__ float g_y[NN_];
__device__ float g_y2[NN_];
__device__ float g_s[6][NN_];
__device__ float g_apA[NC_];
__device__ float g_apB[NC_];
__device__ float g_amax[B_*C_];
__device__ float g_filt[16];
__device__ float g_gb[NEVAL_*128];
__device__ double g_part[B_*64];
__device__ int   g_ctr = 0;
__device__ __align__(16) ull g_wp[WPTOT];

__device__ __forceinline__ float gelu_f(float x){
    return 0.5f * x * (1.0f + erff(x * 0.70710678118654752440f));
}
__device__ __forceinline__ ull bcast2(float x){
    ull r; asm("mov.b64 %0, {%1, %1};" : "=l"(r) : "f"(x)); return r;
}
__device__ __forceinline__ ull pk2(float a, float b){
    ull r; asm("mov.b64 %0, {%1, %2};" : "=l"(r) : "f"(a), "f"(b)); return r;
}
__device__ __forceinline__ void fma2(ull &d, ull a, ull b){
    asm("fma.rn.f32x2 %0, %1, %2, %0;" : "+l"(d) : "l"(a), "l"(b));
}
__device__ __forceinline__ float2 unpk(ull v){
    float lo, hi; asm("mov.b64 {%0, %1}, %2;" : "=f"(lo), "=f"(hi) : "l"(v));
    return make_float2(lo, hi);
}

// ---------------- weight pack: gmem -> ull-pair layout matching smem ----------------
__global__ void kpack(const float* __restrict__ w1, const float* __restrict__ w2,
                      const float* __restrict__ w3, ull* __restrict__ wp){
    int idx = blockIdx.x*256 + threadIdx.x;
    if (idx >= WPTOT) return;
    float wa, wb;
    if (idx < W2P){
        int ci = idx / 96, r = idx - ci*96;
        int k = r >> 5, p = r & 31;
        wa = w1[(size_t)(2*p)  *(CS_*3) + ci*3 + k];
        wb = w1[(size_t)(2*p+1)*(CS_*3) + ci*3 + k];
    } else if (idx < W3P){
        int j = idx - W2P;
        int ci = j / 96, r = j - ci*96;
        int k = r >> 5, p = r & 31;
        wa = w2[(size_t)(2*p)  *(HD_*3) + ci*3 + k];
        wb = w2[(size_t)(2*p+1)*(HD_*3) + ci*3 + k];
    } else {
        int j = idx - W3P;
        int g = j / 6144, r2 = j - g*6144;
        int ci = r2 / 96, r = r2 - ci*96;
        int k = r >> 5, p = r & 31;
        wa = w3[(size_t)(g*64 + 2*p)  *(HD_*3) + ci*3 + k];
        wb = w3[(size_t)(g*64 + 2*p+1)*(HD_*3) + ci*3 + k];
    }
    wp[idx] = pk2(wa, wb);
}

// ---------------- dywan MLP tail (whole block, 256 threads) ----------------
__device__ void dywan_tail(const float* __restrict__ amax,
                           const float* __restrict__ sw1, const float* __restrict__ sb1,
                           const float* __restrict__ sw2, const float* __restrict__ sb2,
                           const float* __restrict__ sw3, const float* __restrict__ sb3,
                           float* __restrict__ filtOut){
    __shared__ float feat[256], g2s[256], raw[128], nrm[16];
    int t = threadIdx.x;
    { int bb = t >> 5, h = t & 31;
      float s = sb1[h];
      const float* am = amax + bb*64; const float* w = sw1 + h*64;
      #pragma unroll 8
      for (int c = 0; c < 64; c++) s += am[c]*w[c];
      feat[t] = gelu_f(s); }
    __syncthreads();
    { int bb = t >> 5, h = t & 31;
      float s = sb2[h];
      #pragma unroll 8
      for (int k = 0; k < 32; k++) s += feat[bb*32+k]*sw2[h*32+k];
      g2s[t] = gelu_f(s); }
    __syncthreads();
    if (t < 128){ int bb = t >> 4, j = t & 15;
      float s = sb3[j];
      #pragma unroll 8
      for (int k = 0; k < 32; k++) s += g2s[bb*32+k]*sw3[j*32+k];
      raw[t] = s; }
    __syncthreads();
    if (t < 16){ int bb = t >> 1, hh = t & 1;
      float s = 0.f;
      for (int j = 0; j < 8; j++){ float v = raw[bb*16 + hh*8 + j]; s += v*v; }
      nrm[t] = sqrtf(s); }
    __syncthreads();
    if (t < 16){ int hh = t >> 3, j = t & 7;
      float s = 0.f;
      for (int bb = 0; bb < 8; bb++) s += raw[bb*16 + hh*8 + j] / nrm[bb*2 + hh];
      filtOut[hh*8 + j] = s * 0.125f; }
}

// ---------------- kprep: amax(x) rows 0-511, gb blocks 512-536, dywan level1 block 537 ----------------
__global__ void kprep(const float* __restrict__ x,
                      const float* __restrict__ tw1, const float* __restrict__ tb1,
                      const float* __restrict__ tw2, const float* __restrict__ tb2,
                      const float* __restrict__ cw,  const float* __restrict__ cb,
                      const float* __restrict__ sw1, const float* __restrict__ sb1,
                      const float* __restrict__ sw2, const float* __restrict__ sb2,
                      const float* __restrict__ sw3, const float* __restrict__ sb3,
                      float* __restrict__ amax, float* __restrict__ gbout,
                      float* __restrict__ filt, int* __restrict__ ctr){
    int t = threadIdx.x;
    if (blockIdx.x < 512){
        int row = blockIdx.x;
        const float* p = x + (size_t)row * L_;
        float m = -3.4e38f;
        for (int i = t; i < L_; i += 256) m = fmaxf(m, p[i]);
        __shared__ float sm[256];
        sm[t] = m; __syncthreads();
        for (int s = 128; s > 0; s >>= 1){
            if (t < s) sm[t] = fmaxf(sm[t], sm[t+s]);
            __syncthreads();
        }
        if (t == 0){
            amax[row] = sm[0];
            __threadfence();
            atomicAdd(ctr, 1);
        }
    } else if (blockIdx.x < 537){
        int e = blockIdx.x - 512;
        const double hs = 0.25;
        double td;
        if (e == 24) td = 1.0;
        else {
            int i = e / 6, s = e % 6;
            double off;
            switch (s){
                case 0: off = 0.0; break;
                case 1: off = hs/5.0; break;
                case 2: off = 3.0*hs/10.0; break;
                case 3: off = 4.0*hs/5.0; break;
                case 4: off = 8.0*hs/9.0; break;
                default: off = hs; break;
            }
            td = (double)i*hs + off;
        }
        float tt = (float)td;
        __shared__ float te1[16], te2[16];
        if (t < 16) te1[t] = gelu_f(tt * tw1[t] + tb1[t]);
        __syncthreads();
        if (t < 16){
            float s = tb2[t];
            #pragma unroll
            for (int k = 0; k < 16; k++) s += te1[k]*tw2[t*16+k];
            te2[t] = s;
        }
        __syncthreads();
        if (t < 128){
            float s = cb[t];
            #pragma unroll
            for (int k = 0; k < 16; k++) s += te2[k]*cw[t*16+k];
            gbout[e*128 + t] = s;
        }
    } else {
        if (t == 0){
            while (atomicAdd(ctr, 0) < 512) __nanosleep(200);
        }
        __syncthreads();
        __threadfence();
        dywan_tail(amax, sw1, sb1, sw2, sb2, sw3, sb3, filt);
        __syncthreads();
        if (t == 0) atomicExch(ctr, 0);
    }
}

// ---------------- kwavF: per-row wavelet conv + row-max + optional next-level dywan ----------------
__global__ void kwavF(const float* __restrict__ src,
                      const float* __restrict__ filtIn,
                      float* __restrict__ apOut, float* __restrict__ stacked,
                      float* __restrict__ amaxNext, int chOff, int copyX, int computeNext,
                      const float* __restrict__ sw1, const float* __restrict__ sb1,
                      const float* __restrict__ sw2, const float* __restrict__ sb2,
                      const float* __restrict__ sw3, const float* __restrict__ sb3,
                      float* __restrict__ filtOut, int* __restrict__ ctr){
    __shared__ float xr[2064];
    __shared__ float red[256];
    __shared__ int lastFlag;
    int t = threadIdx.x;
    int r = blockIdx.x;
    int b = r >> 6, c = r & 63;
    const float* row = src + (size_t)r * L_;

    float f[16];
    #pragma unroll
    for (int i = 0; i < 16; i++) f[i] = filtIn[i];

    for (int s = t; s < 2056; s += 256){
        int gl = s - 3;
        if (gl < 0) gl = -gl;
        if (gl >= L_) gl = 2*L_ - 2 - gl;
        xr[s] = row[gl];
    }
    __syncthreads();

    int l0 = t * 8;
    float xv[16];
    #pragma unroll
    for (int i = 0; i < 4; i++)
        *(float4*)&xv[i*4] = *(const float4*)&xr[l0 + i*4];

    float alo[8], ahi[8];
    float mlo = -3.4e38f;
    #pragma unroll
    for (int j = 0; j < 8; j++){
        float a = 0.f, h = 0.f;
        #pragma unroll
        for (int k = 0; k < 8; k++){
            float v = (j + k < 15) ? xv[j+k] : xr[l0 + j + k];
            a += v * f[k];
            h += v * f[8+k];
        }
        alo[j] = a; ahi[j] = h;
        mlo = fmaxf(mlo, a);
    }
    *(float4*)&apOut[(size_t)r*L_ + l0]     = *(float4*)&alo[0];
    *(float4*)&apOut[(size_t)r*L_ + l0 + 4] = *(float4*)&alo[4];
    float* st = stacked + (((size_t)b*CS_ + chOff + c) << 11) + l0;
    *(float4*)&st[0] = *(float4*)&ahi[0];
    *(float4*)&st[4] = *(float4*)&ahi[4];
    if (copyX){
        float* sx = stacked + (((size_t)b*CS_ + c) << 11) + l0;
        #pragma unroll
        for (int j = 0; j < 8; j++) sx[j] = xr[l0 + 3 + j];
    }
    red[t] = mlo; __syncthreads();
    for (int s = 128; s > 0; s >>= 1){
        if (t < s) red[t] = fmaxf(red[t], red[t+s]);
        __syncthreads();
    }
    if (t == 0) amaxNext[r] = red[0];

    if (computeNext){
        __syncthreads();
        if (t == 0){
            __threadfence();
            int old = atomicAdd(ctr, 1);
            lastFlag = (old == 511) ? 1 : 0;
        }
        __syncthreads();
        if (lastFlag){
            __threadfence();
            dywan_tail(amaxNext, sw1, sb1, sw2, sb2, sw3, sb3, filtOut);
            __syncthreads();
            if (t == 0) atomicExch(ctr, 0);
        }
    }
}

// ---------------- fused ode_f core: 4co x 4l per thread ----------------
template<int NCI>
__device__ __forceinline__ void acc_run(const float* __restrict__ xsm,
                                        const ull* __restrict__ wsp,
                                        int cp0, int l0, ull acc[2][4]){
    #pragma unroll 4
    for (int ci = 0; ci < NCI; ci++){
        const float* xr = xsm + ci*64 + l0;
        float4 xa = *(const float4*)xr;
        float2 xb = *(const float2*)(xr + 4);
        ull q[6];
        q[0]=bcast2(xa.x); q[1]=bcast2(xa.y); q[2]=bcast2(xa.z);
        q[3]=bcast2(xa.w); q[4]=bcast2(xb.x); q[5]=bcast2(xb.y);
        const ull* wr = wsp + ci*96 + cp0;
        ulonglong2 w0 = *(const ulonglong2*)(wr);
        ulonglong2 w1 = *(const ulonglong2*)(wr + 32);
        ulonglong2 w2 = *(const ulonglong2*)(wr + 64);
        #pragma unroll
        for (int l = 0; l < 4; l++){
            fma2(acc[0][l], w0.x, q[l]);   fma2(acc[1][l], w0.y, q[l]);
            fma2(acc[0][l], w1.x, q[l+1]); fma2(acc[1][l], w1.y, q[l+1]);
            fma2(acc[0][l], w2.x, q[l+2]); fma2(acc[1][l], w2.y, q[l+2]);
        }
    }
}

// grid (37, 8), 256 threads; ct = t>>4 (16 co-groups), lt = t&15, 4co x 4l per thread
// slots: x 62 (gl=L0-3+j), h1 60 (gl=L0-2+i), h2 58 (gl=L0-1+i), out 56 (gl=L0+i)
template<int NA, bool YC>
__global__ __launch_bounds__(256, 2)
void kfused(const float* __restrict__ y,
            const float* __restrict__ a1, float c1,
            const float* __restrict__ a2, float c2,
            const float* __restrict__ a3, float c3,
            const float* __restrict__ a4, float c4,
            const float* __restrict__ a5, float c5,
            const ull* __restrict__ wp,
            const float* __restrict__ b1v, const float* __restrict__ b2v,
            const float* __restrict__ b3v,
            const float* __restrict__ gb,
            float* __restrict__ youtg, float* __restrict__ outp){
    extern __shared__ float sm[];
    ull* wsp = (ull*)(sm + WSO);
    ulonglong2* wsp2 = (ulonglong2*)wsp;
    const int t   = threadIdx.x;
    const int ct  = t >> 4;
    const int lt  = t & 15;
    const int co0 = ct * 4;
    const int cp0 = ct * 2;
    const int l0a = lt * 4;
    const int b   = blockIdx.y;
    const int L0  = blockIdx.x * LT_;

    const size_t inOff = (size_t)b * CS_ * L_;
    const float* yb = y + inOff;
    const float* p1 = (NA>=1) ? (a1 + inOff) : yb;
    const float* p2 = (NA>=2) ? (a2 + inOff) : yb;
    const float* p3 = (NA>=3) ? (a3 + inOff) : yb;
    const float* p4 = (NA>=4) ? (a4 + inOff) : yb;
    const float* p5 = (NA>=5) ? (a5 + inOff) : yb;
    float* youtb = YC ? (youtg + inOff) : nullptr;

    // -------- stage 1: 8 ci-chunks, double-buffered --------
    ull acc1[2][4] = {{0,0,0,0},{0,0,0,0}};
    const int l1c = min(l0a, 56);

    auto loadX = [&](int c0, int buf){
        #pragma unroll
        for (int rr = 0; rr < 8; rr++){
            int idx = t + rr*256;
            int ci = idx >> 6, j = idx & 63;
            int gl = L0 - 3 + j;
            float v = 0.f;
            if (j < 62 && ((unsigned)gl < (unsigned)L_)){
                size_t o = (size_t)(c0 + ci) * L_ + (size_t)gl;
                v = yb[o];
                if (NA>=1) v = fmaf(c1, p1[o], v);
                if (NA>=2) v = fmaf(c2, p2[o], v);
                if (NA>=3) v = fmaf(c3, p3[o], v);
                if (NA>=4) v = fmaf(c4, p4[o], v);
                if (NA>=5) v = fmaf(c5, p5[o], v);
                if (YC){ if (j >= 3 && j < 59) youtb[o] = v; }
            }
            sm[XSO + (buf<<11) + idx] = v;
        }
    };
    auto loadW1 = [&](int cchunk, int half){
        const ulonglong2* src = (const ulonglong2*)(wp + W1P) + cchunk*1536;
        #pragma unroll
        for (int rr = 0; rr < 6; rr++){
            int idx = t + rr*256;
            wsp2[half*1536 + idx] = src[idx];
        }
    };

    loadX(0, 0); loadW1(0, 0);
    __syncthreads();
    #pragma unroll 1
    for (int c = 0; c < 8; c++){
        if (c < 7){ loadX((c+1)*32, (c+1)&1); loadW1(c+1, (c+1)&1); }
        acc_run<32>(sm + XSO + ((c&1)<<11), wsp + (c&1)*3072, cp0, l1c, acc1);
        __syncthreads();
    }

    // epilogue 1: bias + FiLM + GELU; zero outside [0,L)
    {
        float v[4][4];
        #pragma unroll
        for (int l = 0; l < 4; l++){
            float2 u0 = unpk(acc1[0][l]), u1 = unpk(acc1[1][l]);
            v[0][l]=u0.x; v[1][l]=u0.y; v[2][l]=u1.x; v[3][l]=u1.y;
        }
        #pragma unroll
        for (int cc = 0; cc < 4; cc++){
            int co = co0 + cc;
            float bia = b1v[co], ga = 1.f + gb[co], be = gb[64+co];
            float4 r;
            float* pr = (float*)&r;
            #pragma unroll
            for (int ll = 0; ll < 4; ll++){
                int gl = L0 - 2 + l1c + ll;
                float h = gelu_f(ga*(v[cc][ll]+bia)+be);
                pr[ll] = ((unsigned)gl < (unsigned)L_) ? h : 0.f;
            }
            *(float4*)&sm[H1O + co*64 + l1c] = r;
        }
    }
    // load w2 packed: 3072 ull2
    {
        const ulonglong2* src = (const ulonglong2*)(wp + W2P);
        #pragma unroll
        for (int rr = 0; rr < 12; rr++){
            int idx = t + rr*256;
            wsp2[idx] = src[idx];
        }
    }
    __syncthreads();

    // -------- stage 2 --------
    {
        ull acc2[2][4] = {{0,0,0,0},{0,0,0,0}};
        const int l2c = min(l0a, 56);
        acc_run<64>(sm + H1O, wsp, cp0, l2c, acc2);
        float v[4][4];
        #pragma unroll
        for (int l = 0; l < 4; l++){
            float2 u0 = unpk(acc2[0][l]), u1 = unpk(acc2[1][l]);
            v[0][l]=u0.x; v[1][l]=u0.y; v[2][l]=u1.x; v[3][l]=u1.y;
        }
        __syncthreads();   // h1 reads done before h2 region reuse is irrelevant; keep order safe
        #pragma unroll
        for (int cc = 0; cc < 4; cc++){
            int co = co0 + cc;
            float bia = b2v[co];
            float4 r;
            float* pr = (float*)&r;
            #pragma unroll
            for (int ll = 0; ll < 4; ll++){
                int gl = L0 - 1 + l2c + ll;
                float h = gelu_f(v[cc][ll]+bia);
                pr[ll] = ((unsigned)gl < (unsigned)L_) ? h : 0.f;
            }
            *(float4*)&sm[H2O + co*64 + l2c] = r;
        }
    }
    __syncthreads();

    // -------- stage 3: 4 co-groups of 64 --------
    const int l3c = min(l0a, 52);
    #pragma unroll 1
    for (int g = 0; g < 4; g++){
        {
            const ulonglong2* src = (const ulonglong2*)(wp + W3P) + g*3072;
            #pragma unroll
            for (int rr = 0; rr < 12; rr++){
                int idx = t + rr*256;
                wsp2[idx] = src[idx];
            }
        }
        __syncthreads();
        ull acc3[2][4] = {{0,0,0,0},{0,0,0,0}};
        acc_run<64>(sm + H2O, wsp, cp0, l3c, acc3);
        int gl0 = L0 + l3c;
        if (gl0 < L_){
            float v[4][4];
            #pragma unroll
            for (int l = 0; l < 4; l++){
                float2 u0 = unpk(acc3[0][l]), u1 = unpk(acc3[1][l]);
                v[0][l]=u0.x; v[1][l]=u0.y; v[2][l]=u1.x; v[3][l]=u1.y;
            }
            #pragma unroll
            for (int cc = 0; cc < 4; cc++){
                int co = g*64 + co0 + cc;
                float bia = b3v[co];
                float4 r = make_float4(v[cc][0]+bia, v[cc][1]+bia,
                                       v[cc][2]+bia, v[cc][3]+bia);
                *(float4*)&outp[((size_t)(b*CS_ + co))*L_ + gl0] = r;
            }
        }
        __syncthreads();
    }
}

// ---------------- ecloss reduction ----------------
__global__ void kinner(const float* __restrict__ a, const float* __restrict__ d,
                       double* __restrict__ part){
    int bb = blockIdx.x, ch = blockIdx.y;
    size_t base = (size_t)bb*CS_*L_ + (size_t)ch*8192;
    double s = 0.0;
    for (int i = threadIdx.x; i < 8192; i += 256)
        s += (double)a[base+i] * (double)d[base+i];
    __shared__ double sm[256];
    sm[threadIdx.x] = s; __syncthreads();
    for (int st = 128; st > 0; st >>= 1){
        if (threadIdx.x < st) sm[threadIdx.x] += sm[threadIdx.x+st];
        __syncthreads();
    }
    if (threadIdx.x == 0) part[bb*64 + ch] = sm[0];
}

__global__ void kfinal(const double* __restrict__ part, float* __restrict__ out){
    if (threadIdx.x == 0){
        double acc = 0.0;
        for (int b = 0; b < 8; b++){
            double s = 0.0;
            for (int j = 0; j < 64; j++) s += part[b*64+j];
            acc += s*s;
        }
        out[4194304] = (float)(acc / 8.0);
    }
}

// ---------------- output permute ----------------
__global__ void kout(const float* __restrict__ y, float* __restrict__ out){
    int i = blockIdx.x*256 + threadIdx.x;
    int l = i & (L_-1); int bc = i >> 11; int c = bc & 255; int b = bc >> 8;
    int g = c >> 6; int cc = c & 63;
    out[(size_t)g*(B_*C_*L_) + (((size_t)b*C_ + cc) << 11) + l] = y[i];
}

// ---------------- host orchestration ----------------
extern "C" void kernel_launch(void* const* d_in, const int* in_sizes, int n_in,
                              void* d_out, int out_size){
    const float* x   = (const float*)d_in[0];
    const float* sw1 = (const float*)d_in[1];
    const float* sb1 = (const float*)d_in[2];
    const float* sw2 = (const float*)d_in[3];
    const float* sb2 = (const float*)d_in[4];
    const float* sw3 = (const float*)d_in[5];
    const float* sb3 = (const float*)d_in[6];
    const float* tw1 = (const float*)d_in[7];
    const float* tb1 = (const float*)d_in[8];
    const float* tw2 = (const float*)d_in[9];
    const float* tb2 = (const float*)d_in[10];
    const float* cw  = (const float*)d_in[11];
    const float* cb  = (const float*)d_in[12];
    const float* k1  = (const float*)d_in[13];
    const float* kb1 = (const float*)d_in[14];
    const float* k2  = (const float*)d_in[15];
    const float* kb2 = (const float*)d_in[16];
    const float* k3  = (const float*)d_in[17];
    const float* kb3 = (const float*)d_in[18];
    float* out = (float*)d_out;

    float *stacked, *y, *y2, *sbase, *apA, *apB, *amax, *filt, *gb;
    double* part; int* ctr; ull* wp;
    cudaGetSymbolAddress((void**)&stacked, g_stacked);
    cudaGetSymbolAddress((void**)&y,       g_y);
    cudaGetSymbolAddress((void**)&y2,      g_y2);
    cudaGetSymbolAddress((void**)&sbase,   g_s);
    cudaGetSymbolAddress((void**)&apA,     g_apA);
    cudaGetSymbolAddress((void**)&apB,     g_apB);
    cudaGetSymbolAddress((void**)&amax,    g_amax);
    cudaGetSymbolAddress((void**)&filt,    g_filt);
    cudaGetSymbolAddress((void**)&gb,      g_gb);
    cudaGetSymbolAddress((void**)&part,    g_part);
    cudaGetSymbolAddress((void**)&ctr,     g_ctr);
    cudaGetSymbolAddress((void**)&wp,      g_wp);

    cudaFuncSetAttribute(kfused<0,false>, cudaFuncAttributeMaxDynamicSharedMemorySize, SMB);
    cudaFuncSetAttribute(kfused<1,false>, cudaFuncAttributeMaxDynamicSharedMemorySize, SMB);
    cudaFuncSetAttribute(kfused<2,false>, cudaFuncAttributeMaxDynamicSharedMemorySize, SMB);
    cudaFuncSetAttribute(kfused<3,false>, cudaFuncAttributeMaxDynamicSharedMemorySize, SMB);
    cudaFuncSetAttribute(kfused<4,false>, cudaFuncAttributeMaxDynamicSharedMemorySize, SMB);
    cudaFuncSetAttribute(kfused<5,false>, cudaFuncAttributeMaxDynamicSharedMemorySize, SMB);
    cudaFuncSetAttribute(kfused<5,true >, cudaFuncAttributeMaxDynamicSharedMemorySize, SMB);

    float* S[6];
    for (int k = 0; k < 6; k++) S[k] = sbase + (size_t)k * NN_;

    // ---- prologue ----
    kpack<<<(WPTOT+255)/256, 256>>>(k1, k2, k3, wp);
    kprep<<<538, 256>>>(x, tw1, tb1, tw2, tb2, cw, cb,
                        sw1, sb1, sw2, sb2, sw3, sb3, amax, gb, filt, ctr);
    kwavF<<<512, 256>>>(x,   filt, apA, stacked, amax, 64,  1, 1,
                        sw1, sb1, sw2, sb2, sw3, sb3, filt, ctr);
    kwavF<<<512, 256>>>(apA, filt, apB, stacked, amax, 128, 0, 1,
                        sw1, sb1, sw2, sb2, sw3, sb3, filt, ctr);
    kwavF<<<512, 256>>>(apB, filt, apA, stacked, amax, 192, 0, 0,
                        sw1, sb1, sw2, sb2, sw3, sb3, filt, ctr);

    const dim3 gF(NBX_, B_);
    const double hs = 0.25;
    const float* Z = nullptr;

    auto ev_plain = [&](int ev, int na, const float* ybase,
                        const float* a1, float c1, const float* a2, float c2,
                        const float* a3, float c3, const float* a4, float c4,
                        const float* a5, float c5, float* sout){
        const float* gbe = gb + ev*128;
        switch (na){
        case 0: kfused<0,false><<<gF,256,SMB>>>(ybase,a1,c1,a2,c2,a3,c3,a4,c4,a5,c5,wp,kb1,kb2,kb3,gbe,nullptr,sout); break;
        case 1: kfused<1,false><<<gF,256,SMB>>>(ybase,a1,c1,a2,c2,a3,c3,a4,c4,a5,c5,wp,kb1,kb2,kb3,gbe,nullptr,sout); break;
        case 2: kfused<2,false><<<gF,256,SMB>>>(ybase,a1,c1,a2,c2,a3,c3,a4,c4,a5,c5,wp,kb1,kb2,kb3,gbe,nullptr,sout); break;
        case 3: kfused<3,false><<<gF,256,SMB>>>(ybase,a1,c1,a2,c2,a3,c3,a4,c4,a5,c5,wp,kb1,kb2,kb3,gbe,nullptr,sout); break;
        case 4: kfused<4,false><<<gF,256,SMB>>>(ybase,a1,c1,a2,c2,a3,c3,a4,c4,a5,c5,wp,kb1,kb2,kb3,gbe,nullptr,sout); break;
        default:kfused<5,false><<<gF,256,SMB>>>(ybase,a1,c1,a2,c2,a3,c3,a4,c4,a5,c5,wp,kb1,kb2,kb3,gbe,nullptr,sout); break;
        }
    };
    auto ev_ycomb = [&](int ev, const float* ybase, float** M, float* yout, float* sout){
        kfused<5,true><<<gF,256,SMB>>>(ybase,
            M[0],(float)(hs*35.0/384.0), M[2],(float)(hs*500.0/1113.0),
            M[3],(float)(hs*125.0/192.0), M[4],(float)(-hs*2187.0/6784.0),
            M[5],(float)(hs*11.0/84.0),
            wp, kb1, kb2, kb3, gb + ev*128, yout, sout);
    };

    float* MA[6] = {S[0],S[1],S[2],S[3],S[4],S[5]};
    float* MB[6] = {S[1],S[0],S[2],S[3],S[4],S[5]};

    auto step_tail = [&](int e, const float* ybase, float** M){
        ev_plain(e+1, 1, ybase, M[0],(float)(hs*1.0/5.0), Z,0,Z,0,Z,0,Z,0, M[1]);
        ev_plain(e+2, 2, ybase, M[0],(float)(hs*3.0/40.0), M[1],(float)(hs*9.0/40.0), Z,0,Z,0,Z,0, M[2]);
        ev_plain(e+3, 3, ybase, M[0],(float)(hs*44.0/45.0), M[1],(float)(-hs*56.0/15.0),
                 M[2],(float)(hs*32.0/9.0), Z,0,Z,0, M[3]);
        ev_plain(e+4, 4, ybase, M[0],(float)(hs*19372.0/6561.0), M[1],(float)(-hs*25360.0/2187.0),
                 M[2],(float)(hs*64448.0/6561.0), M[3],(float)(-hs*212.0/729.0), Z,0, M[4]);
        ev_plain(e+5, 5, ybase, M[0],(float)(hs*9017.0/3168.0), M[1],(float)(-hs*355.0/33.0),
                 M[2],(float)(hs*46732.0/5247.0), M[3],(float)(hs*49.0/176.0),
                 M[4],(float)(-hs*5103.0/18656.0), M[5]);
    };

    ev_plain(0, 0, stacked, Z,0,Z,0,Z,0,Z,0,Z,0, MA[0]);
    step_tail(0, stacked, MA);
    ev_ycomb(6, stacked, MA, y, MB[0]);
    step_tail(6, y, MB);
    ev_ycomb(12, y, MB, y2, MA[0]);
    step_tail(12, y2, MA);
    ev_ycomb(18, y2, MA, y, MB[0]);
    step_tail(18, y, MB);
    ev_ycomb(24, y, MB, y2, S[0]);

    kinner<<<dim3(B_, 64), 256>>>(stacked, S[0], part);
    kout<<<NN_/256, 256>>>(y2, out);
    kfinal<<<1, 32>>>(part, out);
}

// round 11
// speedup vs baseline: 2.6342x; 1.0053x over previous
#include <cuda_runtime.h>
#include <stdint.h>
#include <math.h>

#define B_ 8
#define C_ 64
#define L_ 2048
#define CS_ 256
#define HD_ 64
#define NN_ (B_*CS_*L_)      // 4194304
#define NC_ (B_*C_*L_)       // 1048576
#define NEVAL_ 25
#define LT_ 56               // l-tile per block
#define NBX_ 37              // 37*56 = 2072 >= 2048

// kfused smem layout (floats):
// XS: [0, 8192)    (half*2 + buf)*2048
// H1: [8192,16384) half*4096, row stride 64
// H2: [16384,24576)
// WQ: [24576, 49152) as ull: 4 slots x 3072 ull (24KB each)
#define SMB2 (49152*4)       // 196608 B = 192KB

// packed weights: ONE contiguous stream of 18 parts x 3072 ull
// parts 0-7: w1 (256ci), 8-9: w2 (64ci), 10-17: w3 (4g x 64ci)
#define WPTOT 55296

typedef unsigned long long ull;

__device__ float g_stacked[NN_];
__device__ float g_y[NN_];
__device__ float g_y2[NN_];
__device__ float g_s[6][NN_];
__device__ float g_apA[NC_];
__device__ float g_apB[NC_];
__device__ float g_amax[B_*C_];
__device__ float g_filt[16];
__device__ float g_gb[NEVAL_*128];
__device__ double g_part[B_*64];
__device__ int   g_ctr = 0;
__device__ __align__(16) ull g_wp[WPTOT];

__device__ __forceinline__ float gelu_f(float x){
    return 0.5f * x * (1.0f + erff(x * 0.70710678118654752440f));
}
__device__ __forceinline__ ull bcast2(float x){
    ull r; asm("mov.b64 %0, {%1, %1};" : "=l"(r) : "f"(x)); return r;
}
__device__ __forceinline__ ull pk2(float a, float b){
    ull r; asm("mov.b64 %0, {%1, %2};" : "=l"(r) : "f"(a), "f"(b)); return r;
}
__device__ __forceinline__ void fma2(ull &d, ull a, ull b){
    asm("fma.rn.f32x2 %0, %1, %2, %0;" : "+l"(d) : "l"(a), "l"(b));
}
__device__ __forceinline__ float2 unpk(ull v){
    float lo, hi; asm("mov.b64 {%0, %1}, %2;" : "=f"(lo), "=f"(hi) : "l"(v));
    return make_float2(lo, hi);
}

// ---------------- dywan MLP tail (whole block, 256 threads) ----------------
__device__ void dywan_tail(const float* __restrict__ amax,
                           const float* __restrict__ sw1, const float* __restrict__ sb1,
                           const float* __restrict__ sw2, const float* __restrict__ sb2,
                           const float* __restrict__ sw3, const float* __restrict__ sb3,
                           float* __restrict__ filtOut){
    __shared__ float feat[256], g2s[256], raw[128], nrm[16];
    int t = threadIdx.x;
    { int bb = t >> 5, h = t & 31;
      float s = sb1[h];
      const float* am = amax + bb*64; const float* w = sw1 + h*64;
      #pragma unroll 8
      for (int c = 0; c < 64; c++) s += am[c]*w[c];
      feat[t] = gelu_f(s); }
    __syncthreads();
    { int bb = t >> 5, h = t & 31;
      float s = sb2[h];
      #pragma unroll 8
      for (int k = 0; k < 32; k++) s += feat[bb*32+k]*sw2[h*32+k];
      g2s[t] = gelu_f(s); }
    __syncthreads();
    if (t < 128){ int bb = t >> 4, j = t & 15;
      float s = sb3[j];
      #pragma unroll 8
      for (int k = 0; k < 32; k++) s += g2s[bb*32+k]*sw3[j*32+k];
      raw[t] = s; }
    __syncthreads();
    if (t < 16){ int bb = t >> 1, hh = t & 1;
      float s = 0.f;
      for (int j = 0; j < 8; j++){ float v = raw[bb*16 + hh*8 + j]; s += v*v; }
      nrm[t] = sqrtf(s); }
    __syncthreads();
    if (t < 16){ int hh = t >> 3, j = t & 7;
      float s = 0.f;
      for (int bb = 0; bb < 8; bb++) s += raw[bb*16 + hh*8 + j] / nrm[bb*2 + hh];
      filtOut[hh*8 + j] = s * 0.125f; }
}

// ---------------- kprep: amax rows 0-511, gb 512-536, spin-dywan 537, weight-pack 538+ ----------------
__global__ void kprep(const float* __restrict__ x,
                      const float* __restrict__ tw1, const float* __restrict__ tb1,
                      const float* __restrict__ tw2, const float* __restrict__ tb2,
                      const float* __restrict__ cw,  const float* __restrict__ cb,
                      const float* __restrict__ sw1, const float* __restrict__ sb1,
                      const float* __restrict__ sw2, const float* __restrict__ sb2,
                      const float* __restrict__ sw3, const float* __restrict__ sb3,
                      const float* __restrict__ w1, const float* __restrict__ w2,
                      const float* __restrict__ w3,
                      float* __restrict__ amax, float* __restrict__ gbout,
                      float* __restrict__ filt, ull* __restrict__ wp,
                      int* __restrict__ ctr){
    int t = threadIdx.x;
    if (blockIdx.x < 512){
        int row = blockIdx.x;
        const float* p = x + (size_t)row * L_;
        float m = -3.4e38f;
        for (int i = t; i < L_; i += 256) m = fmaxf(m, p[i]);
        __shared__ float sm[256];
        sm[t] = m; __syncthreads();
        for (int s = 128; s > 0; s >>= 1){
            if (t < s) sm[t] = fmaxf(sm[t], sm[t+s]);
            __syncthreads();
        }
        if (t == 0){
            amax[row] = sm[0];
            __threadfence();
            atomicAdd(ctr, 1);
        }
    } else if (blockIdx.x < 537){
        int e = blockIdx.x - 512;
        const double hs = 0.25;
        double td;
        if (e == 24) td = 1.0;
        else {
            int i = e / 6, s = e % 6;
            double off;
            switch (s){
                case 0: off = 0.0; break;
                case 1: off = hs/5.0; break;
                case 2: off = 3.0*hs/10.0; break;
                case 3: off = 4.0*hs/5.0; break;
                case 4: off = 8.0*hs/9.0; break;
                default: off = hs; break;
            }
            td = (double)i*hs + off;
        }
        float tt = (float)td;
        __shared__ float te1[16], te2[16];
        if (t < 16) te1[t] = gelu_f(tt * tw1[t] + tb1[t]);
        __syncthreads();
        if (t < 16){
            float s = tb2[t];
            #pragma unroll
            for (int k = 0; k < 16; k++) s += te1[k]*tw2[t*16+k];
            te2[t] = s;
        }
        __syncthreads();
        if (t < 128){
            float s = cb[t];
            #pragma unroll
            for (int k = 0; k < 16; k++) s += te2[k]*cw[t*16+k];
            gbout[e*128 + t] = s;
        }
    } else if (blockIdx.x == 537){
        if (t == 0){
            while (atomicAdd(ctr, 0) < 512) __nanosleep(200);
        }
        __syncthreads();
        __threadfence();
        dywan_tail(amax, sw1, sb1, sw2, sb2, sw3, sb3, filt);
        __syncthreads();
        if (t == 0) atomicExch(ctr, 0);
    } else {
        int idx = (blockIdx.x - 538)*256 + t;
        if (idx >= WPTOT) return;
        float wa, wb;
        if (idx < 24576){
            int ci = idx / 96, r = idx - ci*96;
            int k = r >> 5, p = r & 31;
            wa = w1[(size_t)(2*p)  *(CS_*3) + ci*3 + k];
            wb = w1[(size_t)(2*p+1)*(CS_*3) + ci*3 + k];
        } else if (idx < 30720){
            int j = idx - 24576;
            int ci = j / 96, r = j - ci*96;
            int k = r >> 5, p = r & 31;
            wa = w2[(size_t)(2*p)  *(HD_*3) + ci*3 + k];
            wb = w2[(size_t)(2*p+1)*(HD_*3) + ci*3 + k];
        } else {
            int j = idx - 30720;
            int g = j / 6144, r2 = j - g*6144;
            int ci = r2 / 96, r = r2 - ci*96;
            int k = r >> 5, p = r & 31;
            wa = w3[(size_t)(g*64 + 2*p)  *(HD_*3) + ci*3 + k];
            wb = w3[(size_t)(g*64 + 2*p+1)*(HD_*3) + ci*3 + k];
        }
        wp[idx] = pk2(wa, wb);
    }
}

// ---------------- kwavF: per-row wavelet conv + row-max + optional next-level dywan ----------------
__global__ void kwavF(const float* __restrict__ src,
                      const float* __restrict__ filtIn,
                      float* __restrict__ apOut, float* __restrict__ stacked,
                      float* __restrict__ amaxNext, int chOff, int copyX, int computeNext,
                      const float* __restrict__ sw1, const float* __restrict__ sb1,
                      const float* __restrict__ sw2, const float* __restrict__ sb2,
                      const float* __restrict__ sw3, const float* __restrict__ sb3,
                      float* __restrict__ filtOut, int* __restrict__ ctr){
    __shared__ float xr[2064];
    __shared__ float red[256];
    __shared__ int lastFlag;
    int t = threadIdx.x;
    int r = blockIdx.x;
    int b = r >> 6, c = r & 63;
    const float* row = src + (size_t)r * L_;

    float f[16];
    #pragma unroll
    for (int i = 0; i < 16; i++) f[i] = filtIn[i];

    for (int s = t; s < 2056; s += 256){
        int gl = s - 3;
        if (gl < 0) gl = -gl;
        if (gl >= L_) gl = 2*L_ - 2 - gl;
        xr[s] = row[gl];
    }
    __syncthreads();

    int l0 = t * 8;
    float xv[16];
    #pragma unroll
    for (int i = 0; i < 4; i++)
        *(float4*)&xv[i*4] = *(const float4*)&xr[l0 + i*4];

    float alo[8], ahi[8];
    float mlo = -3.4e38f;
    #pragma unroll
    for (int j = 0; j < 8; j++){
        float a = 0.f, h = 0.f;
        #pragma unroll
        for (int k = 0; k < 8; k++){
            float v = (j + k < 15) ? xv[j+k] : xr[l0 + j + k];
            a += v * f[k];
            h += v * f[8+k];
        }
        alo[j] = a; ahi[j] = h;
        mlo = fmaxf(mlo, a);
    }
    *(float4*)&apOut[(size_t)r*L_ + l0]     = *(float4*)&alo[0];
    *(float4*)&apOut[(size_t)r*L_ + l0 + 4] = *(float4*)&alo[4];
    float* st = stacked + (((size_t)b*CS_ + chOff + c) << 11) + l0;
    *(float4*)&st[0] = *(float4*)&ahi[0];
    *(float4*)&st[4] = *(float4*)&ahi[4];
    if (copyX){
        float* sx = stacked + (((size_t)b*CS_ + c) << 11) + l0;
        #pragma unroll
        for (int j = 0; j < 8; j++) sx[j] = xr[l0 + 3 + j];
    }
    red[t] = mlo; __syncthreads();
    for (int s = 128; s > 0; s >>= 1){
        if (t < s) red[t] = fmaxf(red[t], red[t+s]);
        __syncthreads();
    }
    if (t == 0) amaxNext[r] = red[0];

    if (computeNext){
        __syncthreads();
        if (t == 0){
            __threadfence();
            int old = atomicAdd(ctr, 1);
            lastFlag = (old == 511) ? 1 : 0;
        }
        __syncthreads();
        if (lastFlag){
            __threadfence();
            dywan_tail(amaxNext, sw1, sb1, sw2, sb2, sw3, sb3, filtOut);
            __syncthreads();
            if (t == 0) atomicExch(ctr, 0);
        }
    }
}

// ---------------- fused ode_f core: 4co x 4l per thread, 32-ci parts ----------------
__device__ __forceinline__ void acc_run32(const float* __restrict__ xsm,
                                          const ull* __restrict__ wsp,
                                          int cp0, int l0, ull acc[2][4]){
    #pragma unroll 4
    for (int ci = 0; ci < 32; ci++){
        const float* xr = xsm + ci*64 + l0;
        float4 xa = *(const float4*)xr;
        float2 xb = *(const float2*)(xr + 4);
        ull q[6];
        q[0]=bcast2(xa.x); q[1]=bcast2(xa.y); q[2]=bcast2(xa.z);
        q[3]=bcast2(xa.w); q[4]=bcast2(xb.x); q[5]=bcast2(xb.y);
        const ull* wr = wsp + ci*96 + cp0;
        ulonglong2 w0 = *(const ulonglong2*)(wr);
        ulonglong2 w1 = *(const ulonglong2*)(wr + 32);
        ulonglong2 w2 = *(const ulonglong2*)(wr + 64);
        #pragma unroll
        for (int l = 0; l < 4; l++){
            fma2(acc[0][l], w0.x, q[l]);   fma2(acc[1][l], w0.y, q[l]);
            fma2(acc[0][l], w1.x, q[l+1]); fma2(acc[1][l], w1.y, q[l+1]);
            fma2(acc[0][l], w2.x, q[l+2]); fma2(acc[1][l], w2.y, q[l+2]);
        }
    }
}

// grid (37, 4), 512 threads; half = t>>8 owns batch row b = 2*by + half.
// within half: ct = tl>>4 (16 co-groups x 4co), lt = tl&15 (4 l per thread).
// weight stream: 18 parts x 24KB through a 4-slot cp.async ring (depth 3).
// slots: x 62 valid (gl=L0-3+j), h1 60 (gl=L0-2+i), h2 58 (gl=L0-1+i), out 56.
template<int NA, bool YC>
__global__ __launch_bounds__(512, 1)
void kfused(const float* __restrict__ y,
            const float* __restrict__ a1, float c1,
            const float* __restrict__ a2, float c2,
            const float* __restrict__ a3, float c3,
            const float* __restrict__ a4, float c4,
            const float* __restrict__ a5, float c5,
            const ull* __restrict__ wp,
            const float* __restrict__ b1v, const float* __restrict__ b2v,
            const float* __restrict__ b3v,
            const float* __restrict__ gb,
            float* __restrict__ youtg, float* __restrict__ outp){
    extern __shared__ float sm[];
    const int t    = threadIdx.x;
    const int half = t >> 8;
    const int tl   = t & 255;
    const int ct   = tl >> 4;
    const int lt   = tl & 15;
    const int co0  = ct * 4;
    const int cp0  = ct * 2;
    const int l0a  = lt * 4;
    const int b    = blockIdx.y*2 + half;
    const int L0   = blockIdx.x * LT_;

    float* xsh = sm + half*4096;            // 2 bufs x 2048 per half
    float* h1s = sm + 8192  + half*4096;
    float* h2s = sm + 16384 + half*4096;
    ull*   wq  = (ull*)(sm + 24576);

    unsigned int smbase;
    asm("{ .reg .u64 tt; cvta.to.shared.u64 tt, %1; cvt.u32.u64 %0, tt; }"
        : "=r"(smbase) : "l"(sm));
    const unsigned int smW = smbase + 24576u*4u;

    const size_t inOff = (size_t)b * CS_ * L_;
    const float* yb = y + inOff;
    const float* p1 = (NA>=1) ? (a1 + inOff) : yb;
    const float* p2 = (NA>=2) ? (a2 + inOff) : yb;
    const float* p3 = (NA>=3) ? (a3 + inOff) : yb;
    const float* p4 = (NA>=4) ? (a4 + inOff) : yb;
    const float* p5 = (NA>=5) ? (a5 + inOff) : yb;
    float* youtb = YC ? (youtg + inOff) : nullptr;

    auto loadX = [&](int c0, int buf){
        float* dst = xsh + buf*2048;
        #pragma unroll
        for (int rr = 0; rr < 8; rr++){
            int idx = tl + rr*256;
            int ci = idx >> 6, j = idx & 63;
            int gl = L0 - 3 + j;
            float v = 0.f;
            if (j < 62 && ((unsigned)gl < (unsigned)L_)){
                size_t o = (size_t)(c0 + ci) * L_ + (size_t)gl;
                v = yb[o];
                if (NA>=1) v = fmaf(c1, p1[o], v);
                if (NA>=2) v = fmaf(c2, p2[o], v);
                if (NA>=3) v = fmaf(c3, p3[o], v);
                if (NA>=4) v = fmaf(c4, p4[o], v);
                if (NA>=5) v = fmaf(c5, p5[o], v);
                if (YC){ if (j >= 3 && j < 59) youtb[o] = v; }
            }
            dst[idx] = v;
        }
    };
    auto issueW = [&](int p){
        const char* src = (const char*)(wp + (size_t)p * 3072);
        unsigned int dbase = smW + (unsigned int)((p & 3) * 3072) * 8u;
        #pragma unroll
        for (int i = 0; i < 3; i++){
            int idx = t + i*512;
            asm volatile("cp.async.cg.shared.global [%0], [%1], 16;"
                :: "r"(dbase + (unsigned int)idx*16u), "l"(src + (size_t)idx*16));
        }
        asm volatile("cp.async.commit_group;");
    };

    issueW(0); issueW(1); issueW(2);
    loadX(0, 0);

    ull acc[2][4];
    const int l1c = min(l0a, 56);
    const int l3c = min(l0a, 52);

    #pragma unroll 1
    for (int p = 0; p < 18; p++){
        if (p < 16)       asm volatile("cp.async.wait_group 2;");
        else if (p == 16) asm volatile("cp.async.wait_group 1;");
        else              asm volatile("cp.async.wait_group 0;");
        __syncthreads();
        if (p + 3 < 18) issueW(p + 3);
        if (p < 7) loadX((p+1)*32, (p+1)&1);

        if (p == 0 || p == 8 || p == 10 || p == 12 || p == 14 || p == 16){
            #pragma unroll
            for (int a = 0; a < 2; a++)
                #pragma unroll
                for (int l = 0; l < 4; l++) acc[a][l] = 0ULL;
        }

        const ull* wslot = wq + (p & 3) * 3072;
        const float* xin;
        int lc;
        if (p < 8)      { xin = xsh + (p&1)*2048;        lc = l1c; }
        else if (p < 10){ xin = h1s + (p-8)*2048;        lc = l1c; }   // l2c == l1c == min(l0a,56)
        else            { xin = h2s + ((p-10)&1)*2048;   lc = l3c; }
        acc_run32(xin, wslot, cp0, lc, acc);

        if (p == 7){
            // epilogue 1: bias + FiLM + GELU -> h1 (zero outside [0,L))
            float v[4][4];
            #pragma unroll
            for (int l = 0; l < 4; l++){
                float2 u0 = unpk(acc[0][l]), u1 = unpk(acc[1][l]);
                v[0][l]=u0.x; v[1][l]=u0.y; v[2][l]=u1.x; v[3][l]=u1.y;
            }
            #pragma unroll
            for (int cc = 0; cc < 4; cc++){
                int co = co0 + cc;
                float bia = b1v[co], ga = 1.f + gb[co], be = gb[64+co];
                float4 r;
                float* pr = (float*)&r;
                #pragma unroll
                for (int ll = 0; ll < 4; ll++){
                    int gl = L0 - 2 + l1c + ll;
                    float h = gelu_f(ga*(v[cc][ll]+bia)+be);
                    pr[ll] = ((unsigned)gl < (unsigned)L_) ? h : 0.f;
                }
                *(float4*)&h1s[co*64 + l1c] = r;
            }
        } else if (p == 9){
            // epilogue 2: bias + GELU -> h2 (zero outside [0,L))
            float v[4][4];
            #pragma unroll
            for (int l = 0; l < 4; l++){
                float2 u0 = unpk(acc[0][l]), u1 = unpk(acc[1][l]);
                v[0][l]=u0.x; v[1][l]=u0.y; v[2][l]=u1.x; v[3][l]=u1.y;
            }
            #pragma unroll
            for (int cc = 0; cc < 4; cc++){
                int co = co0 + cc;
                float bia = b2v[co];
                float4 r;
                float* pr = (float*)&r;
                #pragma unroll
                for (int ll = 0; ll < 4; ll++){
                    int gl = L0 - 1 + l1c + ll;
                    float h = gelu_f(v[cc][ll]+bia);
                    pr[ll] = ((unsigned)gl < (unsigned)L_) ? h : 0.f;
                }
                *(float4*)&h2s[co*64 + l1c] = r;
            }
        } else if (p >= 11 && (p & 1)){
            // stage-3 output for group g
            int g = (p - 11) >> 1;
            int gl0 = L0 + l3c;
            if (gl0 < L_){
                float v[4][4];
                #pragma unroll
                for (int l = 0; l < 4; l++){
                    float2 u0 = unpk(acc[0][l]), u1 = unpk(acc[1][l]);
                    v[0][l]=u0.x; v[1][l]=u0.y; v[2][l]=u1.x; v[3][l]=u1.y;
                }
                #pragma unroll
                for (int cc = 0; cc < 4; cc++){
                    int co = g*64 + co0 + cc;
                    float bia = b3v[co];
                    float4 r = make_float4(v[cc][0]+bia, v[cc][1]+bia,
                                           v[cc][2]+bia, v[cc][3]+bia);
                    *(float4*)&outp[((size_t)(b*CS_ + co))*L_ + gl0] = r;
                }
            }
        }
    }
}

// ---------------- ecloss reduction ----------------
__global__ void kinner(const float* __restrict__ a, const float* __restrict__ d,
                       double* __restrict__ part){
    int bb = blockIdx.x, ch = blockIdx.y;
    size_t base = (size_t)bb*CS_*L_ + (size_t)ch*8192;
    double s = 0.0;
    for (int i = threadIdx.x; i < 8192; i += 256)
        s += (double)a[base+i] * (double)d[base+i];
    __shared__ double sm[256];
    sm[threadIdx.x] = s; __syncthreads();
    for (int st = 128; st > 0; st >>= 1){
        if (threadIdx.x < st) sm[threadIdx.x] += sm[threadIdx.x+st];
        __syncthreads();
    }
    if (threadIdx.x == 0) part[bb*64 + ch] = sm[0];
}

__global__ void kfinal(const double* __restrict__ part, float* __restrict__ out){
    if (threadIdx.x == 0){
        double acc = 0.0;
        for (int b = 0; b < 8; b++){
            double s = 0.0;
            for (int j = 0; j < 64; j++) s += part[b*64+j];
            acc += s*s;
        }
        out[4194304] = (float)(acc / 8.0);
    }
}

// ---------------- output permute ----------------
__global__ void kout(const float* __restrict__ y, float* __restrict__ out){
    int i = blockIdx.x*256 + threadIdx.x;
    int l = i & (L_-1); int bc = i >> 11; int c = bc & 255; int b = bc >> 8;
    int g = c >> 6; int cc = c & 63;
    out[(size_t)g*(B_*C_*L_) + (((size_t)b*C_ + cc) << 11) + l] = y[i];
}

// ---------------- host orchestration ----------------
extern "C" void kernel_launch(void* const* d_in, const int* in_sizes, int n_in,
                              void* d_out, int out_size){
    const float* x   = (const float*)d_in[0];
    const float* sw1 = (const float*)d_in[1];
    const float* sb1 = (const float*)d_in[2];
    const float* sw2 = (const float*)d_in[3];
    const float* sb2 = (const float*)d_in[4];
    const float* sw3 = (const float*)d_in[5];
    const float* sb3 = (const float*)d_in[6];
    const float* tw1 = (const float*)d_in[7];
    const float* tb1 = (const float*)d_in[8];
    const float* tw2 = (const float*)d_in[9];
    const float* tb2 = (const float*)d_in[10];
    const float* cw  = (const float*)d_in[11];
    const float* cb  = (const float*)d_in[12];
    const float* k1  = (const float*)d_in[13];
    const float* kb1 = (const float*)d_in[14];
    const float* k2  = (const float*)d_in[15];
    const float* kb2 = (const float*)d_in[16];
    const float* k3  = (const float*)d_in[17];
    const float* kb3 = (const float*)d_in[18];
    float* out = (float*)d_out;

    float *stacked, *y, *y2, *sbase, *apA, *apB, *amax, *filt, *gb;
    double* part; int* ctr; ull* wp;
    cudaGetSymbolAddress((void**)&stacked, g_stacked);
    cudaGetSymbolAddress((void**)&y,       g_y);
    cudaGetSymbolAddress((void**)&y2,      g_y2);
    cudaGetSymbolAddress((void**)&sbase,   g_s);
    cudaGetSymbolAddress((void**)&apA,     g_apA);
    cudaGetSymbolAddress((void**)&apB,     g_apB);
    cudaGetSymbolAddress((void**)&amax,    g_amax);
    cudaGetSymbolAddress((void**)&filt,    g_filt);
    cudaGetSymbolAddress((void**)&gb,      g_gb);
    cudaGetSymbolAddress((void**)&part,    g_part);
    cudaGetSymbolAddress((void**)&ctr,     g_ctr);
    cudaGetSymbolAddress((void**)&wp,      g_wp);

    cudaFuncSetAttribute(kfused<0,false>, cudaFuncAttributeMaxDynamicSharedMemorySize, SMB2);
    cudaFuncSetAttribute(kfused<1,false>, cudaFuncAttributeMaxDynamicSharedMemorySize, SMB2);
    cudaFuncSetAttribute(kfused<2,false>, cudaFuncAttributeMaxDynamicSharedMemorySize, SMB2);
    cudaFuncSetAttribute(kfused<3,false>, cudaFuncAttributeMaxDynamicSharedMemorySize, SMB2);
    cudaFuncSetAttribute(kfused<4,false>, cudaFuncAttributeMaxDynamicSharedMemorySize, SMB2);
    cudaFuncSetAttribute(kfused<5,false>, cudaFuncAttributeMaxDynamicSharedMemorySize, SMB2);
    cudaFuncSetAttribute(kfused<5,true >, cudaFuncAttributeMaxDynamicSharedMemorySize, SMB2);

    float* S[6];
    for (int k = 0; k < 6; k++) S[k] = sbase + (size_t)k * NN_;

    // ---- prologue: 4 launches ----
    kprep<<<754, 256>>>(x, tw1, tb1, tw2, tb2, cw, cb,
                        sw1, sb1, sw2, sb2, sw3, sb3, k1, k2, k3,
                        amax, gb, filt, wp, ctr);
    kwavF<<<512, 256>>>(x,   filt, apA, stacked, amax, 64,  1, 1,
                        sw1, sb1, sw2, sb2, sw3, sb3, filt, ctr);
    kwavF<<<512, 256>>>(apA, filt, apB, stacked, amax, 128, 0, 1,
                        sw1, sb1, sw2, sb2, sw3, sb3, filt, ctr);
    kwavF<<<512, 256>>>(apB, filt, apA, stacked, amax, 192, 0, 0,
                        sw1, sb1, sw2, sb2, sw3, sb3, filt, ctr);

    const dim3 gF(NBX_, 4);
    const double hs = 0.25;
    const float* Z = nullptr;

    auto ev_plain = [&](int ev, int na, const float* ybase,
                        const float* a1, float c1, const float* a2, float c2,
                        const float* a3, float c3, const float* a4, float c4,
                        const float* a5, float c5, float* sout){
        const float* gbe = gb + ev*128;
        switch (na){
        case 0: kfused<0,false><<<gF,512,SMB2>>>(ybase,a1,c1,a2,c2,a3,c3,a4,c4,a5,c5,wp,kb1,kb2,kb3,gbe,nullptr,sout); break;
        case 1: kfused<1,false><<<gF,512,SMB2>>>(ybase,a1,c1,a2,c2,a3,c3,a4,c4,a5,c5,wp,kb1,kb2,kb3,gbe,nullptr,sout); break;
        case 2: kfused<2,false><<<gF,512,SMB2>>>(ybase,a1,c1,a2,c2,a3,c3,a4,c4,a5,c5,wp,kb1,kb2,kb3,gbe,nullptr,sout); break;
        case 3: kfused<3,false><<<gF,512,SMB2>>>(ybase,a1,c1,a2,c2,a3,c3,a4,c4,a5,c5,wp,kb1,kb2,kb3,gbe,nullptr,sout); break;
        case 4: kfused<4,false><<<gF,512,SMB2>>>(ybase,a1,c1,a2,c2,a3,c3,a4,c4,a5,c5,wp,kb1,kb2,kb3,gbe,nullptr,sout); break;
        default:kfused<5,false><<<gF,512,SMB2>>>(ybase,a1,c1,a2,c2,a3,c3,a4,c4,a5,c5,wp,kb1,kb2,kb3,gbe,nullptr,sout); break;
        }
    };
    auto ev_ycomb = [&](int ev, const float* ybase, float** M, float* yout, float* sout){
        kfused<5,true><<<gF,512,SMB2>>>(ybase,
            M[0],(float)(hs*35.0/384.0), M[2],(float)(hs*500.0/1113.0),
            M[3],(float)(hs*125.0/192.0), M[4],(float)(-hs*2187.0/6784.0),
            M[5],(float)(hs*11.0/84.0),
            wp, kb1, kb2, kb3, gb + ev*128, yout, sout);
    };

    float* MA[6] = {S[0],S[1],S[2],S[3],S[4],S[5]};
    float* MB[6] = {S[1],S[0],S[2],S[3],S[4],S[5]};

    auto step_tail = [&](int e, const float* ybase, float** M){
        ev_plain(e+1, 1, ybase, M[0],(float)(hs*1.0/5.0), Z,0,Z,0,Z,0,Z,0, M[1]);
        ev_plain(e+2, 2, ybase, M[0],(float)(hs*3.0/40.0), M[1],(float)(hs*9.0/40.0), Z,0,Z,0,Z,0, M[2]);
        ev_plain(e+3, 3, ybase, M[0],(float)(hs*44.0/45.0), M[1],(float)(-hs*56.0/15.0),
                 M[2],(float)(hs*32.0/9.0), Z,0,Z,0, M[3]);
        ev_plain(e+4, 4, ybase, M[0],(float)(hs*19372.0/6561.0), M[1],(float)(-hs*25360.0/2187.0),
                 M[2],(float)(hs*64448.0/6561.0), M[3],(float)(-hs*212.0/729.0), Z,0, M[4]);
        ev_plain(e+5, 5, ybase, M[0],(float)(hs*9017.0/3168.0), M[1],(float)(-hs*355.0/33.0),
                 M[2],(float)(hs*46732.0/5247.0), M[3],(float)(hs*49.0/176.0),
                 M[4],(float)(-hs*5103.0/18656.0), M[5]);
    };

    ev_plain(0, 0, stacked, Z,0,Z,0,Z,0,Z,0,Z,0, MA[0]);
    step_tail(0, stacked, MA);
    ev_ycomb(6, stacked, MA, y, MB[0]);
    step_tail(6, y, MB);
    ev_ycomb(12, y, MB, y2, MA[0]);
    step_tail(12, y2, MA);
    ev_ycomb(18, y2, MA, y, MB[0]);
    step_tail(18, y, MB);
    ev_ycomb(24, y, MB, y2, S[0]);

    kinner<<<dim3(B_, 64), 256>>>(stacked, S[0], part);
    kout<<<NN_/256, 256>>>(y2, out);
    kfinal<<<1, 32>>>(part, out);
}